// round 8
// baseline (speedup 1.0000x reference)
#include <cuda_runtime.h>
#include <cuda_fp16.h>
#include <math.h>

// ConvCaps EM routing (b=8, B=C=32, K=3, s=2, Win=13, Wout=6, 3 EM iters).
// R8: d-split across lanes. Block = (n,xy), 512 thr, 16 warps = (o-slice, c-half),
// lane = (dh, c16): each thread computes 8 of 16 d's -> moment regs halved ->
// <=64 regs -> 2 blocks/SM = 32 warps/SM (2x occupancy vs R4/R7).
// W fp16 [oij][dh][c][q][p2]: ONE LDG.128 per position per thread.
// p_hat block-local in smem; grid barrier only for the D normalizer.

#define RP0 (1.0f / 1152.0f)
#define LOG2PI 1.8378770664093453f
typedef unsigned long long ull;

__device__ __half g_Wh[147456];  // [oij][dh][c][q][pl]  (uint4 per (oij,dh,c))
__device__ float g_D0[43264];    // [n][o][13][13]
__device__ float g_D1[43264];
__device__ unsigned g_bar[2];

// -------- prep: W relayout+fp16, zero D + barrier counters --------
__global__ void prep_kernel(const float* __restrict__ W) {
    int idx = blockIdx.x * 256 + threadIdx.x;   // 576*256 = 147456
    if (idx < 147456) {
        int pl  = idx & 1;
        int q   = (idx >> 1) & 3;
        int c   = (idx >> 3) & 31;
        int dh  = (idx >> 8) & 1;
        int oij = idx >> 9;
        int o = oij / 9, ij = oij - o * 9;
        int p = dh * 2 + pl;
        // src: W[i,j,o,c,p,q]
        g_Wh[idx] = __float2half_rn(W[(((ij * 32 + o) * 32 + c) * 4 + p) * 4 + q]);
    }
    if (idx < 43264) { g_D0[idx] = 0.0f; g_D1[idx] = 0.0f; }
    if (idx < 2) g_bar[idx] = 0u;
}

// -------- packed f32x2 helpers --------
__device__ __forceinline__ ull f2fma(ull a, ull b, ull c) {
    ull d; asm("fma.rn.f32x2 %0, %1, %2, %3;" : "=l"(d) : "l"(a), "l"(b), "l"(c)); return d;
}
__device__ __forceinline__ ull f2mul(ull a, ull b) {
    ull d; asm("mul.rn.f32x2 %0, %1, %2;" : "=l"(d) : "l"(a), "l"(b)); return d;
}
__device__ __forceinline__ ull f2add(ull a, ull b) {
    ull d; asm("add.rn.f32x2 %0, %1, %2;" : "=l"(d) : "l"(a), "l"(b)); return d;
}
__device__ __forceinline__ ull f2pack(float lo, float hi) {
    ull d; asm("mov.b64 %0, {%1, %2};" : "=l"(d) : "f"(lo), "f"(hi)); return d;
}
__device__ __forceinline__ void f2unpack(float& lo, float& hi, ull v) {
    asm("mov.b64 {%0, %1}, %2;" : "=f"(lo), "=f"(hi) : "l"(v));
}
__device__ __forceinline__ ull h2w(unsigned u) {     // half2 -> packed f32x2
    __half2 h = *reinterpret_cast<__half2*>(&u);
    float2 f = __half22float2(h);
    return f2pack(f.x, f.y);
}

// smem float offsets
#define SM_POSE2 0        // [oij][qr][2] duplicated pose: 9216
#define SM_A     9216     // 288
#define SM_AD    9504     // 288
#define SM_PH    9792     // [oij][33] p_hat (red 16*32*17=8704 aliased): 9504
#define SM_MOM   19296    // [c][33]: 1056
#define SM_MU    20352    // [c][17]: 544
#define SM_SFAC  20896    // 32
#define SMEM_FLOATS 20928

__global__ void __launch_bounds__(512, 2) fused_kernel(
    const float* __restrict__ x,
    const float* __restrict__ bv_p,
    const float* __restrict__ ba_p,
    const float* __restrict__ lam_p,
    float* __restrict__ out)
{
    extern __shared__ float sm[];
    float* pose2  = sm + SM_POSE2;
    float* a_s    = sm + SM_A;
    float* aD_s   = sm + SM_AD;
    float* ph_s   = sm + SM_PH;
    float* red    = ph_s;          // aliased: red live only between M and stats
    float* mom    = sm + SM_MOM;
    float* mu_s   = sm + SM_MU;
    float* sfac_s = sm + SM_SFAC;

    const int xy = blockIdx.x;     // 0..35
    const int n  = blockIdx.y;     // 0..7
    const int X = xy / 6, Y = xy % 6;
    const int tid = threadIdx.x;   // 0..511
    const int w = tid >> 5;        // 0..15
    const int osl = w >> 1;        // o-slice 0..7 (4 o each)
    const int ch = w & 1;          // c-half
    const int lane = tid & 31;
    const int dh = lane >> 4;      // d-half: p-pair (dh*2, dh*2+1)
    const int c16 = lane & 15;
    const int c = ch * 16 + c16;   // output capsule 0..31

    const float* xn = x + n * (544 * 169);
    const int base = (2 * X) * 13 + 2 * Y;

    // ---- load patch: duplicated pose (qr-inner), act ----
    {
        int qr = tid & 15, o = tid >> 4;   // exactly 512 elems
        const float* src = xn + (qr * 32 + o) * 169 + base;
        #pragma unroll
        for (int i = 0; i < 3; i++)
            #pragma unroll
            for (int j = 0; j < 3; j++) {
                float v = src[i * 13 + j];
                int off = (o * 9 + i * 3 + j) * 32 + qr * 2;
                pose2[off] = v; pose2[off + 1] = v;
            }
    }
    if (tid < 288) {
        int o = tid / 9, ij = tid - o * 9;
        float av = xn[(512 + o) * 169 + base + (ij / 3) * 13 + (ij % 3)];
        a_s[tid] = av;
        aD_s[tid] = av * RP0;      // iter0: rh = ph(=1) * aD
    }
    for (int e = tid; e < 9504; e += 512) ph_s[e] = 1.0f;
    __syncthreads();

    const float bv = bv_p[0], ba = ba_p[0], lam = lam_p[0];

    for (int it = 0; it < 3; it++) {
        // ================= M phase (8 d's per thread) =================
        ull m1[4], m2[4];
        #pragma unroll
        for (int r = 0; r < 4; r++) { m1[r] = 0ull; m2[r] = 0ull; }
        float sumr = 0.0f;

        #pragma unroll 1
        for (int oo = 0; oo < 4; oo++) {
            int o = osl * 4 + oo;
            #pragma unroll 3
            for (int ij = 0; ij < 9; ij++) {
                int oij = o * 9 + ij;
                float rh = ph_s[oij * 33 + c] * aD_s[oij];
                sumr += rh;
                ull rh2 = f2pack(rh, rh);
                uint4 wr = ((const uint4*)g_Wh)[(oij * 2 + dh) * 32 + c];
                const ulonglong2* pb2 = (const ulonglong2*)(pose2 + oij * 32);
                ull v[4];
                {
                    ull wq = h2w(wr.x);              // q=0: (p_lo, p_hi)
                    ulonglong2 pA = pb2[0], pB = pb2[1];
                    v[0] = f2mul(wq, pA.x); v[1] = f2mul(wq, pA.y);
                    v[2] = f2mul(wq, pB.x); v[3] = f2mul(wq, pB.y);
                }
                {
                    ull wq = h2w(wr.y);
                    ulonglong2 pA = pb2[2], pB = pb2[3];
                    v[0] = f2fma(wq, pA.x, v[0]); v[1] = f2fma(wq, pA.y, v[1]);
                    v[2] = f2fma(wq, pB.x, v[2]); v[3] = f2fma(wq, pB.y, v[3]);
                }
                {
                    ull wq = h2w(wr.z);
                    ulonglong2 pA = pb2[4], pB = pb2[5];
                    v[0] = f2fma(wq, pA.x, v[0]); v[1] = f2fma(wq, pA.y, v[1]);
                    v[2] = f2fma(wq, pB.x, v[2]); v[3] = f2fma(wq, pB.y, v[3]);
                }
                {
                    ull wq = h2w(wr.w);
                    ulonglong2 pA = pb2[6], pB = pb2[7];
                    v[0] = f2fma(wq, pA.x, v[0]); v[1] = f2fma(wq, pA.y, v[1]);
                    v[2] = f2fma(wq, pB.x, v[2]); v[3] = f2fma(wq, pB.y, v[3]);
                }
                #pragma unroll
                for (int r = 0; r < 4; r++) {
                    ull t = f2mul(rh2, v[r]);
                    m1[r] = f2add(m1[r], t);
                    m2[r] = f2fma(t, v[r], m2[r]);
                }
            }
        }
        __syncthreads();   // all ph reads done before red overwrites it

        // red[w][lane][17]: slots 0..7 m1 (dloc), 8..15 m2, 16 sumr
        {
            float* myred = red + (w * 32 + lane) * 17;
            #pragma unroll
            for (int r = 0; r < 4; r++) {
                float lo, hi;
                f2unpack(lo, hi, m1[r]); myred[r]     = lo; myred[4 + r]  = hi;
                f2unpack(lo, hi, m2[r]); myred[8 + r] = lo; myred[12 + r] = hi;
            }
            myred[16] = sumr;
        }
        __syncthreads();
        // gather mom[c][33] from the (osl, ch, dh) decomposition
        for (int s = tid; s < 1056; s += 512) {
            int cc = s / 33, f = s - cc * 33;
            int chh = cc >> 4, cl = cc & 15;
            int slot, ln;
            if (f < 16)      { slot = f & 7;          ln = (f >> 3) * 16 + cl; }
            else if (f < 32) { slot = 8 + ((f-16)&7); ln = ((f-16) >> 3) * 16 + cl; }
            else             { slot = 16;             ln = cl; }
            float acc = 0.0f;
            #pragma unroll
            for (int os = 0; os < 8; os++)
                acc += red[((os * 2 + chh) * 32 + ln) * 17 + slot];
            mom[s] = acc;
        }
        __syncthreads();

        // ================= stats (32 threads) =================
        if (tid < 32) {
            const float* mm = mom + tid * 33;
            float R = mm[32];
            float invR = 1.0f / R;
            float cs = 0.0f;
            #pragma unroll
            for (int d = 0; d < 16; d++) {
                float m  = mm[d] * invR;
                float sg = fmaf(-m, m, mm[16 + d] * invR);
                mu_s[tid * 17 + d] = m;
                cs += __logf(sg);
            }
            float cost = R * fmaf(16.0f, bv, cs);
            float act  = 1.0f / (1.0f + __expf(lam * (cost - ba)));
            if (it == 2) {
                float* on = out + (long)n * 19584 + xy;
                #pragma unroll
                for (int d = 0; d < 16; d++)
                    on[(tid * 16 + d) * 36] = mu_s[tid * 17 + d];
                on[(512 + tid) * 36] = act;
            } else {
                sfac_s[tid] = act * __expf(-0.5f * fmaf(16.0f, LOG2PI, cs));
            }
        }
        __syncthreads();
        if (it == 2) return;

        // ================= E phase =================
        {
            float sf = sfac_s[c];
            ull nmu[4];
            #pragma unroll
            for (int r = 0; r < 4; r++)
                nmu[r] = f2pack(-mu_s[c * 17 + dh * 8 + r],
                                -mu_s[c * 17 + dh * 8 + 4 + r]);
            #pragma unroll 1
            for (int oo = 0; oo < 4; oo++) {
                int o = osl * 4 + oo;
                #pragma unroll 3
                for (int ij = 0; ij < 9; ij++) {
                    int oij = o * 9 + ij;
                    uint4 wr = ((const uint4*)g_Wh)[(oij * 2 + dh) * 32 + c];
                    const ulonglong2* pb2 = (const ulonglong2*)(pose2 + oij * 32);
                    ull v[4];
                    {
                        ull wq = h2w(wr.x);
                        ulonglong2 pA = pb2[0], pB = pb2[1];
                        v[0] = f2mul(wq, pA.x); v[1] = f2mul(wq, pA.y);
                        v[2] = f2mul(wq, pB.x); v[3] = f2mul(wq, pB.y);
                    }
                    {
                        ull wq = h2w(wr.y);
                        ulonglong2 pA = pb2[2], pB = pb2[3];
                        v[0] = f2fma(wq, pA.x, v[0]); v[1] = f2fma(wq, pA.y, v[1]);
                        v[2] = f2fma(wq, pB.x, v[2]); v[3] = f2fma(wq, pB.y, v[3]);
                    }
                    {
                        ull wq = h2w(wr.z);
                        ulonglong2 pA = pb2[4], pB = pb2[5];
                        v[0] = f2fma(wq, pA.x, v[0]); v[1] = f2fma(wq, pA.y, v[1]);
                        v[2] = f2fma(wq, pB.x, v[2]); v[3] = f2fma(wq, pB.y, v[3]);
                    }
                    {
                        ull wq = h2w(wr.w);
                        ulonglong2 pA = pb2[6], pB = pb2[7];
                        v[0] = f2fma(wq, pA.x, v[0]); v[1] = f2fma(wq, pA.y, v[1]);
                        v[2] = f2fma(wq, pB.x, v[2]); v[3] = f2fma(wq, pB.y, v[3]);
                    }
                    ull ssd2;
                    {
                        ull dd = f2add(v[0], nmu[0]);
                        ssd2 = f2mul(dd, dd);
                    }
                    #pragma unroll
                    for (int r = 1; r < 4; r++) {
                        ull dd = f2add(v[r], nmu[r]);
                        ssd2 = f2fma(dd, dd, ssd2);
                    }
                    float slo, shi; f2unpack(slo, shi, ssd2);
                    float shalf = slo + shi;
                    float stot = shalf + __shfl_xor_sync(0xffffffffu, shalf, 16);
                    float ph = sf * __expf(-stot);
                    // kperm=[0,2,1] self-inverse: file p_hat at permuted slot
                    int i2 = ij / 3, j2 = ij - i2 * 3;
                    if (dh == 0)
                        ph_s[(o * 9 + ((3 - i2) % 3) * 3 + ((3 - j2) % 3)) * 33 + c] = ph;
                }
            }
        }
        __syncthreads();

        // ---- D pass: row sums -> global atomics ----
        float* Dg = (it == 0) ? g_D0 : g_D1;
        if (tid < 288) {
            const float* pr = ph_s + tid * 33;
            float s = 0.0f;
            #pragma unroll
            for (int k = 0; k < 32; k++) s += pr[k];
            int o = tid / 9, ij = tid - o * 9;
            atomicAdd(&Dg[(n * 32 + o) * 169 + (2 * X + ij / 3) * 13 + (2 * Y + ij % 3)], s);
        }

        // ---- grid barrier (288 blocks, 2/SM provably co-resident) ----
        __syncthreads();
        if (tid == 0) {
            __threadfence();
            atomicAdd(&g_bar[it], 1u);
            while (*((volatile unsigned*)&g_bar[it]) < 288u) { __nanosleep(32); }
        }
        __syncthreads();

        // ---- aD pass: a / D ----
        if (tid < 288) {
            int o = tid / 9, ij = tid - o * 9;
            float Dv = __ldcg(&Dg[(n * 32 + o) * 169 + (2 * X + ij / 3) * 13 + (2 * Y + ij % 3)]);
            aD_s[tid] = __fdividef(a_s[tid], Dv);
        }
        __syncthreads();
    }
}

extern "C" void kernel_launch(void* const* d_in, const int* in_sizes, int n_in,
                              void* d_out, int out_size) {
    const float* x   = (const float*)d_in[0];
    const float* W   = (const float*)d_in[1];
    const float* bv  = (const float*)d_in[2];
    const float* ba  = (const float*)d_in[3];
    const float* lam = (const float*)d_in[4];
    float* out = (float*)d_out;

    const int smem = SMEM_FLOATS * 4;   // 83712 B
    cudaFuncSetAttribute(fused_kernel, cudaFuncAttributeMaxDynamicSharedMemorySize, smem);

    prep_kernel<<<576, 256>>>(W);
    fused_kernel<<<dim3(36, 8), 512, smem>>>(x, bv, ba, lam, out);
}

// round 9
// speedup vs baseline: 1.0666x; 1.0666x over previous
#include <cuda_runtime.h>
#include <cuda_fp16.h>
#include <math.h>

// ConvCaps EM routing (b=8, B=C=32, K=3, s=2, Win=13, Wout=6, 3 EM iters).
// R9: 384 thr (12 warps), 2 blocks/SM -> 24 warps/SM, 85-reg cap (no spill).
// M phase: d-split across warp parity (accumulators 17 floats/thread).
// E phase: position-split (full d per thread, no cross-warp exchange).
// W fp16 [oij][dh][c][q][pl]; pose duplicated in smem (broadcast LDS.128).
// p_hat block-local in smem; grid barrier only for the D normalizer.

#define RP0 (1.0f / 1152.0f)
#define LOG2PI 1.8378770664093453f
typedef unsigned long long ull;

__device__ __half g_Wh[147456];  // [oij][dh][c][q][pl]  (uint4 per (oij,dh,c))
__device__ float g_D0[43264];    // [n][o][13][13]
__device__ float g_D1[43264];
__device__ unsigned g_bar[2];

// -------- prep: W relayout+fp16, zero D + barrier counters --------
__global__ void prep_kernel(const float* __restrict__ W) {
    int idx = blockIdx.x * 256 + threadIdx.x;   // 576*256 = 147456
    if (idx < 147456) {
        int pl  = idx & 1;
        int q   = (idx >> 1) & 3;
        int c   = (idx >> 3) & 31;
        int dh  = (idx >> 8) & 1;
        int oij = idx >> 9;
        int o = oij / 9, ij = oij - o * 9;
        int p = dh * 2 + pl;
        // src: W[i,j,o,c,p,q]
        g_Wh[idx] = __float2half_rn(W[(((ij * 32 + o) * 32 + c) * 4 + p) * 4 + q]);
    }
    if (idx < 43264) { g_D0[idx] = 0.0f; g_D1[idx] = 0.0f; }
    if (idx < 2) g_bar[idx] = 0u;
}

// -------- packed f32x2 helpers --------
__device__ __forceinline__ ull f2fma(ull a, ull b, ull c) {
    ull d; asm("fma.rn.f32x2 %0, %1, %2, %3;" : "=l"(d) : "l"(a), "l"(b), "l"(c)); return d;
}
__device__ __forceinline__ ull f2mul(ull a, ull b) {
    ull d; asm("mul.rn.f32x2 %0, %1, %2;" : "=l"(d) : "l"(a), "l"(b)); return d;
}
__device__ __forceinline__ ull f2add(ull a, ull b) {
    ull d; asm("add.rn.f32x2 %0, %1, %2;" : "=l"(d) : "l"(a), "l"(b)); return d;
}
__device__ __forceinline__ ull f2pack(float lo, float hi) {
    ull d; asm("mov.b64 %0, {%1, %2};" : "=l"(d) : "f"(lo), "f"(hi)); return d;
}
__device__ __forceinline__ void f2unpack(float& lo, float& hi, ull v) {
    asm("mov.b64 {%0, %1}, %2;" : "=f"(lo), "=f"(hi) : "l"(v));
}
__device__ __forceinline__ ull h2w(unsigned u) {     // half2 -> packed f32x2
    __half2 h = *reinterpret_cast<__half2*>(&u);
    float2 f = __half22float2(h);
    return f2pack(f.x, f.y);
}

// smem float offsets
#define SM_POSE2 0        // [oij][qr][2] duplicated pose: 9216
#define SM_A     9216     // 288
#define SM_AD    9504     // 288
#define SM_PH    9792     // [oij][33] p_hat (red 12*32*17=6528 aliased): 9504
#define SM_MOM   19296    // [c][33]: 1056
#define SM_MU    20352    // [c][17]: 544
#define SM_SFAC  20896    // 32
#define SMEM_FLOATS 20928

__global__ void __launch_bounds__(384, 2) fused_kernel(
    const float* __restrict__ x,
    const float* __restrict__ bv_p,
    const float* __restrict__ ba_p,
    const float* __restrict__ lam_p,
    float* __restrict__ out)
{
    extern __shared__ float sm[];
    float* pose2  = sm + SM_POSE2;
    float* a_s    = sm + SM_A;
    float* aD_s   = sm + SM_AD;
    float* ph_s   = sm + SM_PH;
    float* red    = ph_s;          // aliased: red live only between M and stats
    float* mom    = sm + SM_MOM;
    float* mu_s   = sm + SM_MU;
    float* sfac_s = sm + SM_SFAC;

    const int xy = blockIdx.x;     // 0..35
    const int n  = blockIdx.y;     // 0..7
    const int X = xy / 6, Y = xy % 6;
    const int tid = threadIdx.x;   // 0..383
    const int w = tid >> 5;        // 0..11
    const int grp = w >> 1;        // warp pair 0..5 -> 48 positions each
    const int dh = w & 1;          // M-phase d-half (p-pair 2dh, 2dh+1)
    const int c = tid & 31;        // lane = output capsule

    const float* xn = x + n * (544 * 169);
    const int base = (2 * X) * 13 + 2 * Y;

    // ---- load patch: duplicated pose (qr-inner), act ----
    for (int e = tid; e < 512; e += 384) {
        int qr = e & 15, o = e >> 4;
        const float* src = xn + (qr * 32 + o) * 169 + base;
        #pragma unroll
        for (int i = 0; i < 3; i++)
            #pragma unroll
            for (int j = 0; j < 3; j++) {
                float v = src[i * 13 + j];
                int off = (o * 9 + i * 3 + j) * 32 + qr * 2;
                pose2[off] = v; pose2[off + 1] = v;
            }
    }
    if (tid < 288) {
        int o = tid / 9, ij = tid - o * 9;
        float av = xn[(512 + o) * 169 + base + (ij / 3) * 13 + (ij % 3)];
        a_s[tid] = av;
        aD_s[tid] = av * RP0;      // iter0: rh = ph(=1) * aD
    }
    for (int e = tid; e < 9504; e += 384) ph_s[e] = 1.0f;
    __syncthreads();

    const float bv = bv_p[0], ba = ba_p[0], lam = lam_p[0];

    for (int it = 0; it < 3; it++) {
        // ====== M phase: warp does 48 positions, 8 d's (its dh half) ======
        ull m1[4], m2[4];
        #pragma unroll
        for (int r = 0; r < 4; r++) { m1[r] = 0ull; m2[r] = 0ull; }
        float sumr = 0.0f;

        #pragma unroll 4
        for (int k = 0; k < 48; k++) {
            int oij = grp * 48 + k;
            float rh = ph_s[oij * 33 + c] * aD_s[oij];
            sumr += rh;
            ull rh2 = f2pack(rh, rh);
            uint4 wr = ((const uint4*)g_Wh)[(oij * 2 + dh) * 32 + c];
            const ulonglong2* pb2 = (const ulonglong2*)(pose2 + oij * 32);
            ull v[4];
            {
                ull wq = h2w(wr.x);              // q=0: (p_lo, p_hi)
                ulonglong2 pA = pb2[0], pB = pb2[1];
                v[0] = f2mul(wq, pA.x); v[1] = f2mul(wq, pA.y);
                v[2] = f2mul(wq, pB.x); v[3] = f2mul(wq, pB.y);
            }
            {
                ull wq = h2w(wr.y);
                ulonglong2 pA = pb2[2], pB = pb2[3];
                v[0] = f2fma(wq, pA.x, v[0]); v[1] = f2fma(wq, pA.y, v[1]);
                v[2] = f2fma(wq, pB.x, v[2]); v[3] = f2fma(wq, pB.y, v[3]);
            }
            {
                ull wq = h2w(wr.z);
                ulonglong2 pA = pb2[4], pB = pb2[5];
                v[0] = f2fma(wq, pA.x, v[0]); v[1] = f2fma(wq, pA.y, v[1]);
                v[2] = f2fma(wq, pB.x, v[2]); v[3] = f2fma(wq, pB.y, v[3]);
            }
            {
                ull wq = h2w(wr.w);
                ulonglong2 pA = pb2[6], pB = pb2[7];
                v[0] = f2fma(wq, pA.x, v[0]); v[1] = f2fma(wq, pA.y, v[1]);
                v[2] = f2fma(wq, pB.x, v[2]); v[3] = f2fma(wq, pB.y, v[3]);
            }
            #pragma unroll
            for (int r = 0; r < 4; r++) {
                ull t = f2mul(rh2, v[r]);
                m1[r] = f2add(m1[r], t);
                m2[r] = f2fma(t, v[r], m2[r]);
            }
        }
        __syncthreads();   // all ph reads done before red overwrites it

        // red[w][c][17]: slots 0..7 m1 (d = 8*dh + s), 8..15 m2, 16 sumr
        {
            float* myred = red + (w * 32 + c) * 17;
            #pragma unroll
            for (int r = 0; r < 4; r++) {
                float lo, hi;
                f2unpack(lo, hi, m1[r]); myred[r]     = lo; myred[4 + r]  = hi;
                f2unpack(lo, hi, m2[r]); myred[8 + r] = lo; myred[12 + r] = hi;
            }
            myred[16] = sumr;
        }
        __syncthreads();
        // gather mom[c][33]: sum over the 6 warp pairs
        for (int s = tid; s < 1056; s += 384) {
            int cc = s / 33, f = s - cc * 33;
            int slot, dhh;
            if (f < 16)      { dhh = f >> 3;        slot = f & 7; }
            else if (f < 32) { dhh = (f - 16) >> 3; slot = 8 + ((f - 16) & 7); }
            else             { dhh = 0;             slot = 16; }
            float acc = 0.0f;
            #pragma unroll
            for (int g = 0; g < 6; g++)
                acc += red[((g * 2 + dhh) * 32 + cc) * 17 + slot];
            mom[s] = acc;
        }
        __syncthreads();

        // ================= stats (32 threads) =================
        if (tid < 32) {
            const float* mm = mom + tid * 33;
            float R = mm[32];
            float invR = 1.0f / R;
            float cs = 0.0f;
            #pragma unroll
            for (int d = 0; d < 16; d++) {
                float m  = mm[d] * invR;
                float sg = fmaf(-m, m, mm[16 + d] * invR);
                mu_s[tid * 17 + d] = m;
                cs += __logf(sg);
            }
            float cost = R * fmaf(16.0f, bv, cs);
            float act  = 1.0f / (1.0f + __expf(lam * (cost - ba)));
            if (it == 2) {
                float* on = out + (long)n * 19584 + xy;
                #pragma unroll
                for (int d = 0; d < 16; d++)
                    on[(tid * 16 + d) * 36] = mu_s[tid * 17 + d];
                on[(512 + tid) * 36] = act;
            } else {
                sfac_s[tid] = act * __expf(-0.5f * fmaf(16.0f, LOG2PI, cs));
            }
        }
        __syncthreads();
        if (it == 2) return;

        // ====== E phase: warp does 24 positions, FULL 16 d per thread ======
        {
            float sf = sfac_s[c];
            ull nmu[2][4];
            #pragma unroll
            for (int hh = 0; hh < 2; hh++)
                #pragma unroll
                for (int r = 0; r < 4; r++)
                    nmu[hh][r] = f2pack(-mu_s[c * 17 + hh * 8 + r],
                                        -mu_s[c * 17 + hh * 8 + 4 + r]);
            #pragma unroll 2
            for (int k = 0; k < 24; k++) {
                int oij = grp * 48 + dh * 24 + k;
                const ulonglong2* pb2 = (const ulonglong2*)(pose2 + oij * 32);
                uint4 wrA = ((const uint4*)g_Wh)[(oij * 2 + 0) * 32 + c];
                uint4 wrB = ((const uint4*)g_Wh)[(oij * 2 + 1) * 32 + c];
                ull vA[4], vB[4];
                {
                    ull wa = h2w(wrA.x), wb = h2w(wrB.x);
                    ulonglong2 pA = pb2[0], pB = pb2[1];
                    vA[0] = f2mul(wa, pA.x); vB[0] = f2mul(wb, pA.x);
                    vA[1] = f2mul(wa, pA.y); vB[1] = f2mul(wb, pA.y);
                    vA[2] = f2mul(wa, pB.x); vB[2] = f2mul(wb, pB.x);
                    vA[3] = f2mul(wa, pB.y); vB[3] = f2mul(wb, pB.y);
                }
                {
                    ull wa = h2w(wrA.y), wb = h2w(wrB.y);
                    ulonglong2 pA = pb2[2], pB = pb2[3];
                    vA[0] = f2fma(wa, pA.x, vA[0]); vB[0] = f2fma(wb, pA.x, vB[0]);
                    vA[1] = f2fma(wa, pA.y, vA[1]); vB[1] = f2fma(wb, pA.y, vB[1]);
                    vA[2] = f2fma(wa, pB.x, vA[2]); vB[2] = f2fma(wb, pB.x, vB[2]);
                    vA[3] = f2fma(wa, pB.y, vA[3]); vB[3] = f2fma(wb, pB.y, vB[3]);
                }
                {
                    ull wa = h2w(wrA.z), wb = h2w(wrB.z);
                    ulonglong2 pA = pb2[4], pB = pb2[5];
                    vA[0] = f2fma(wa, pA.x, vA[0]); vB[0] = f2fma(wb, pA.x, vB[0]);
                    vA[1] = f2fma(wa, pA.y, vA[1]); vB[1] = f2fma(wb, pA.y, vB[1]);
                    vA[2] = f2fma(wa, pB.x, vA[2]); vB[2] = f2fma(wb, pB.x, vB[2]);
                    vA[3] = f2fma(wa, pB.y, vA[3]); vB[3] = f2fma(wb, pB.y, vB[3]);
                }
                {
                    ull wa = h2w(wrA.w), wb = h2w(wrB.w);
                    ulonglong2 pA = pb2[6], pB = pb2[7];
                    vA[0] = f2fma(wa, pA.x, vA[0]); vB[0] = f2fma(wb, pA.x, vB[0]);
                    vA[1] = f2fma(wa, pA.y, vA[1]); vB[1] = f2fma(wb, pA.y, vB[1]);
                    vA[2] = f2fma(wa, pB.x, vA[2]); vB[2] = f2fma(wb, pB.x, vB[2]);
                    vA[3] = f2fma(wa, pB.y, vA[3]); vB[3] = f2fma(wb, pB.y, vB[3]);
                }
                ull ssd2;
                {
                    ull dd = f2add(vA[0], nmu[0][0]);
                    ssd2 = f2mul(dd, dd);
                }
                #pragma unroll
                for (int r = 1; r < 4; r++) {
                    ull dd = f2add(vA[r], nmu[0][r]);
                    ssd2 = f2fma(dd, dd, ssd2);
                }
                #pragma unroll
                for (int r = 0; r < 4; r++) {
                    ull dd = f2add(vB[r], nmu[1][r]);
                    ssd2 = f2fma(dd, dd, ssd2);
                }
                float slo, shi; f2unpack(slo, shi, ssd2);
                float ph = sf * __expf(-(slo + shi));
                // kperm=[0,2,1] self-inverse: file p_hat at permuted slot
                int o = oij / 9, ij = oij - o * 9;
                int i2 = ij / 3, j2 = ij - i2 * 3;
                ph_s[(o * 9 + ((3 - i2) % 3) * 3 + ((3 - j2) % 3)) * 33 + c] = ph;
            }
        }
        __syncthreads();

        // ---- D pass: row sums -> global atomics ----
        float* Dg = (it == 0) ? g_D0 : g_D1;
        if (tid < 288) {
            const float* pr = ph_s + tid * 33;
            float s = 0.0f;
            #pragma unroll
            for (int k = 0; k < 32; k++) s += pr[k];
            int o = tid / 9, ij = tid - o * 9;
            atomicAdd(&Dg[(n * 32 + o) * 169 + (2 * X + ij / 3) * 13 + (2 * Y + ij % 3)], s);
        }

        // ---- grid barrier (288 blocks, 2/SM provably co-resident) ----
        __syncthreads();
        if (tid == 0) {
            __threadfence();
            atomicAdd(&g_bar[it], 1u);
            while (*((volatile unsigned*)&g_bar[it]) < 288u) { __nanosleep(32); }
        }
        __syncthreads();

        // ---- aD pass: a / D ----
        if (tid < 288) {
            int o = tid / 9, ij = tid - o * 9;
            float Dv = __ldcg(&Dg[(n * 32 + o) * 169 + (2 * X + ij / 3) * 13 + (2 * Y + ij % 3)]);
            aD_s[tid] = __fdividef(a_s[tid], Dv);
        }
        __syncthreads();
    }
}

extern "C" void kernel_launch(void* const* d_in, const int* in_sizes, int n_in,
                              void* d_out, int out_size) {
    const float* x   = (const float*)d_in[0];
    const float* W   = (const float*)d_in[1];
    const float* bv  = (const float*)d_in[2];
    const float* ba  = (const float*)d_in[3];
    const float* lam = (const float*)d_in[4];
    float* out = (float*)d_out;

    const int smem = SMEM_FLOATS * 4;   // 83712 B
    cudaFuncSetAttribute(fused_kernel, cudaFuncAttributeMaxDynamicSharedMemorySize, smem);

    prep_kernel<<<576, 256>>>(W);
    fused_kernel<<<dim3(36, 8), 384, smem>>>(x, bv, ba, lam, out);
}

// round 10
// speedup vs baseline: 1.1329x; 1.0621x over previous
#include <cuda_runtime.h>
#include <cuda_fp16.h>
#include <math.h>

// ConvCaps EM routing (b=8, B=C=32, K=3, s=2, Win=13, Wout=6, 3 EM iters).
// R10: R4 shape (256 thr, 8 warps, 2 blk/SM) + software-pipelined W prefetch.
// W fp16 [oij][dh][c][q][pl]: 2 x LDG.128 per position, next position's W
// loaded before computing current -> covers L2 hit latency per warp.
// p_hat block-local in smem; grid barrier only for the D normalizer.

#define RP0 (1.0f / 1152.0f)
#define LOG2PI 1.8378770664093453f
typedef unsigned long long ull;

__device__ __half g_Wh[147456];  // [oij][dh][c][q][pl]  (uint4 per (oij,dh,c))
__device__ float g_D0[43264];    // [n][o][13][13]
__device__ float g_D1[43264];
__device__ unsigned g_bar[2];

// -------- prep: W relayout+fp16, zero D + barrier counters --------
__global__ void prep_kernel(const float* __restrict__ W) {
    int idx = blockIdx.x * 256 + threadIdx.x;   // 576*256 = 147456
    if (idx < 147456) {
        int pl  = idx & 1;
        int q   = (idx >> 1) & 3;
        int c   = (idx >> 3) & 31;
        int dh  = (idx >> 8) & 1;
        int oij = idx >> 9;
        int o = oij / 9, ij = oij - o * 9;
        int p = dh * 2 + pl;
        // src: W[i,j,o,c,p,q]
        g_Wh[idx] = __float2half_rn(W[(((ij * 32 + o) * 32 + c) * 4 + p) * 4 + q]);
    }
    if (idx < 43264) { g_D0[idx] = 0.0f; g_D1[idx] = 0.0f; }
    if (idx < 2) g_bar[idx] = 0u;
}

// -------- packed f32x2 helpers --------
__device__ __forceinline__ ull f2fma(ull a, ull b, ull c) {
    ull d; asm("fma.rn.f32x2 %0, %1, %2, %3;" : "=l"(d) : "l"(a), "l"(b), "l"(c)); return d;
}
__device__ __forceinline__ ull f2mul(ull a, ull b) {
    ull d; asm("mul.rn.f32x2 %0, %1, %2;" : "=l"(d) : "l"(a), "l"(b)); return d;
}
__device__ __forceinline__ ull f2add(ull a, ull b) {
    ull d; asm("add.rn.f32x2 %0, %1, %2;" : "=l"(d) : "l"(a), "l"(b)); return d;
}
__device__ __forceinline__ ull f2pack(float lo, float hi) {
    ull d; asm("mov.b64 %0, {%1, %2};" : "=l"(d) : "f"(lo), "f"(hi)); return d;
}
__device__ __forceinline__ void f2unpack(float& lo, float& hi, ull v) {
    asm("mov.b64 {%0, %1}, %2;" : "=f"(lo), "=f"(hi) : "l"(v));
}
__device__ __forceinline__ ull h2w(unsigned u) {     // half2 -> packed f32x2
    __half2 h = *reinterpret_cast<__half2*>(&u);
    float2 f = __half22float2(h);
    return f2pack(f.x, f.y);
}

// smem float offsets
#define SM_POSE2 0        // [oij][qr][2] duplicated pose: 9216
#define SM_A     9216     // 288
#define SM_AD    9504     // 288
#define SM_PH    9792     // [oij][33] p_hat (red 8*1056=8448 aliased): 9504
#define SM_MOM   19296    // [c][33]: 1056
#define SM_MU    20352    // [c][17]: 544
#define SM_SFAC  20896    // 32
#define SMEM_FLOATS 20928

__global__ void __launch_bounds__(256, 2) fused_kernel(
    const float* __restrict__ x,
    const float* __restrict__ bv_p,
    const float* __restrict__ ba_p,
    const float* __restrict__ lam_p,
    float* __restrict__ out)
{
    extern __shared__ float sm[];
    float* pose2  = sm + SM_POSE2;
    float* a_s    = sm + SM_A;
    float* aD_s   = sm + SM_AD;
    float* ph_s   = sm + SM_PH;
    float* red    = ph_s;          // aliased: red live only between M and stats
    float* mom    = sm + SM_MOM;
    float* mu_s   = sm + SM_MU;
    float* sfac_s = sm + SM_SFAC;

    const int xy = blockIdx.x;     // 0..35
    const int n  = blockIdx.y;     // 0..7
    const int X = xy / 6, Y = xy % 6;
    const int tid = threadIdx.x;
    const int w = tid >> 5;        // warp 0..7 -> positions w*36 .. w*36+35
    const int c = tid & 31;        // lane = output capsule

    const float* xn = x + n * (544 * 169);
    const int base = (2 * X) * 13 + 2 * Y;

    // ---- load patch: duplicated pose (qr-inner), act ----
    for (int e = tid; e < 512; e += 256) {
        int qr = e & 15, o = e >> 4;
        const float* src = xn + (qr * 32 + o) * 169 + base;
        #pragma unroll
        for (int i = 0; i < 3; i++)
            #pragma unroll
            for (int j = 0; j < 3; j++) {
                float v = src[i * 13 + j];
                int off = (o * 9 + i * 3 + j) * 32 + qr * 2;
                pose2[off] = v; pose2[off + 1] = v;
            }
    }
    for (int e = tid; e < 288; e += 256) {
        int o = e / 9, ij = e - o * 9;
        float av = xn[(512 + o) * 169 + base + (ij / 3) * 13 + (ij % 3)];
        a_s[e] = av;
        aD_s[e] = av * RP0;        // iter0: rh = ph(=1) * aD
    }
    for (int e = tid; e < 9504; e += 256) ph_s[e] = 1.0f;
    __syncthreads();

    const float bv = bv_p[0], ba = ba_p[0], lam = lam_p[0];
    // W base for this warp's 36 positions: uint4 index (oij*2 + dh)*32 + c
    const uint4* wbase = (const uint4*)g_Wh + (w * 36) * 64 + c;

    for (int it = 0; it < 3; it++) {
        // ================= M phase (pipelined W prefetch) =================
        ull m1a[4], m1b[4], m2a[4], m2b[4];
        #pragma unroll
        for (int r = 0; r < 4; r++) { m1a[r]=0ull; m1b[r]=0ull; m2a[r]=0ull; m2b[r]=0ull; }
        float sumr = 0.0f;

        uint4 wA = wbase[0], wB = wbase[32];
        #pragma unroll 4
        for (int k = 0; k < 36; k++) {
            uint4 wAn = wA, wBn = wB;
            if (k < 35) { wAn = wbase[(k + 1) * 64]; wBn = wbase[(k + 1) * 64 + 32]; }
            int oij = w * 36 + k;
            float rh = ph_s[oij * 33 + c] * aD_s[oij];
            sumr += rh;
            ull rh2 = f2pack(rh, rh);
            const ulonglong2* pb2 = (const ulonglong2*)(pose2 + oij * 32);
            ull v0[4], v1[4];
            {
                ull wqA = h2w(wA.x), wqB = h2w(wB.x);
                ulonglong2 pA = pb2[0], pB = pb2[1];
                v0[0] = f2mul(wqA, pA.x); v1[0] = f2mul(wqB, pA.x);
                v0[1] = f2mul(wqA, pA.y); v1[1] = f2mul(wqB, pA.y);
                v0[2] = f2mul(wqA, pB.x); v1[2] = f2mul(wqB, pB.x);
                v0[3] = f2mul(wqA, pB.y); v1[3] = f2mul(wqB, pB.y);
            }
            {
                ull wqA = h2w(wA.y), wqB = h2w(wB.y);
                ulonglong2 pA = pb2[2], pB = pb2[3];
                v0[0] = f2fma(wqA, pA.x, v0[0]); v1[0] = f2fma(wqB, pA.x, v1[0]);
                v0[1] = f2fma(wqA, pA.y, v0[1]); v1[1] = f2fma(wqB, pA.y, v1[1]);
                v0[2] = f2fma(wqA, pB.x, v0[2]); v1[2] = f2fma(wqB, pB.x, v1[2]);
                v0[3] = f2fma(wqA, pB.y, v0[3]); v1[3] = f2fma(wqB, pB.y, v1[3]);
            }
            {
                ull wqA = h2w(wA.z), wqB = h2w(wB.z);
                ulonglong2 pA = pb2[4], pB = pb2[5];
                v0[0] = f2fma(wqA, pA.x, v0[0]); v1[0] = f2fma(wqB, pA.x, v1[0]);
                v0[1] = f2fma(wqA, pA.y, v0[1]); v1[1] = f2fma(wqB, pA.y, v1[1]);
                v0[2] = f2fma(wqA, pB.x, v0[2]); v1[2] = f2fma(wqB, pB.x, v1[2]);
                v0[3] = f2fma(wqA, pB.y, v0[3]); v1[3] = f2fma(wqB, pB.y, v1[3]);
            }
            {
                ull wqA = h2w(wA.w), wqB = h2w(wB.w);
                ulonglong2 pA = pb2[6], pB = pb2[7];
                v0[0] = f2fma(wqA, pA.x, v0[0]); v1[0] = f2fma(wqB, pA.x, v1[0]);
                v0[1] = f2fma(wqA, pA.y, v0[1]); v1[1] = f2fma(wqB, pA.y, v1[1]);
                v0[2] = f2fma(wqA, pB.x, v0[2]); v1[2] = f2fma(wqB, pB.x, v1[2]);
                v0[3] = f2fma(wqA, pB.y, v0[3]); v1[3] = f2fma(wqB, pB.y, v1[3]);
            }
            #pragma unroll
            for (int r = 0; r < 4; r++) {
                ull t0 = f2mul(rh2, v0[r]);
                m1a[r] = f2add(m1a[r], t0);
                m2a[r] = f2fma(t0, v0[r], m2a[r]);
                ull t1 = f2mul(rh2, v1[r]);
                m1b[r] = f2add(m1b[r], t1);
                m2b[r] = f2fma(t1, v1[r], m2b[r]);
            }
            wA = wAn; wB = wBn;
        }
        __syncthreads();   // all ph reads done before red overwrites it

        // pair layout: v0[r] = (d=r, d=4+r), v1[r] = (d=8+r, d=12+r)
        {
            float* myred = red + (w * 32 + c) * 33;
            #pragma unroll
            for (int r = 0; r < 4; r++) {
                float lo, hi;
                f2unpack(lo, hi, m1a[r]); myred[r]      = lo; myred[4 + r]  = hi;
                f2unpack(lo, hi, m1b[r]); myred[8 + r]  = lo; myred[12 + r] = hi;
                f2unpack(lo, hi, m2a[r]); myred[16 + r] = lo; myred[20 + r] = hi;
                f2unpack(lo, hi, m2b[r]); myred[24 + r] = lo; myred[28 + r] = hi;
            }
            myred[32] = sumr;
        }
        __syncthreads();
        for (int s = tid; s < 1056; s += 256) {
            float acc = 0.0f;
            #pragma unroll
            for (int ww = 0; ww < 8; ww++) acc += red[ww * 1056 + s];
            mom[s] = acc;
        }
        __syncthreads();

        // ================= stats =================
        if (tid < 32) {
            const float* mm = mom + tid * 33;
            float R = mm[32];
            float invR = 1.0f / R;
            float cs = 0.0f;
            #pragma unroll
            for (int d = 0; d < 16; d++) {
                float m  = mm[d] * invR;
                float sg = fmaf(-m, m, mm[16 + d] * invR);
                mu_s[tid * 17 + d] = m;
                cs += __logf(sg);
            }
            float cost = R * fmaf(16.0f, bv, cs);
            float act  = 1.0f / (1.0f + __expf(lam * (cost - ba)));
            if (it == 2) {
                float* on = out + (long)n * 19584 + xy;
                #pragma unroll
                for (int d = 0; d < 16; d++)
                    on[(tid * 16 + d) * 36] = mu_s[tid * 17 + d];
                on[(512 + tid) * 36] = act;
            } else {
                sfac_s[tid] = act * __expf(-0.5f * fmaf(16.0f, LOG2PI, cs));
            }
        }
        __syncthreads();
        if (it == 2) return;

        // ================= E phase (pipelined W prefetch) =================
        {
            float sf = sfac_s[c];
            ull nmu0[4], nmu1[4];
            #pragma unroll
            for (int r = 0; r < 4; r++) {
                nmu0[r] = f2pack(-mu_s[c * 17 + r],     -mu_s[c * 17 + 4 + r]);
                nmu1[r] = f2pack(-mu_s[c * 17 + 8 + r], -mu_s[c * 17 + 12 + r]);
            }
            uint4 wA = wbase[0], wB = wbase[32];
            #pragma unroll 4
            for (int k = 0; k < 36; k++) {
                uint4 wAn = wA, wBn = wB;
                if (k < 35) { wAn = wbase[(k + 1) * 64]; wBn = wbase[(k + 1) * 64 + 32]; }
                int oij = w * 36 + k;
                const ulonglong2* pb2 = (const ulonglong2*)(pose2 + oij * 32);
                ull v0[4], v1[4];
                {
                    ull wqA = h2w(wA.x), wqB = h2w(wB.x);
                    ulonglong2 pA = pb2[0], pB = pb2[1];
                    v0[0] = f2mul(wqA, pA.x); v1[0] = f2mul(wqB, pA.x);
                    v0[1] = f2mul(wqA, pA.y); v1[1] = f2mul(wqB, pA.y);
                    v0[2] = f2mul(wqA, pB.x); v1[2] = f2mul(wqB, pB.x);
                    v0[3] = f2mul(wqA, pB.y); v1[3] = f2mul(wqB, pB.y);
                }
                {
                    ull wqA = h2w(wA.y), wqB = h2w(wB.y);
                    ulonglong2 pA = pb2[2], pB = pb2[3];
                    v0[0] = f2fma(wqA, pA.x, v0[0]); v1[0] = f2fma(wqB, pA.x, v1[0]);
                    v0[1] = f2fma(wqA, pA.y, v0[1]); v1[1] = f2fma(wqB, pA.y, v1[1]);
                    v0[2] = f2fma(wqA, pB.x, v0[2]); v1[2] = f2fma(wqB, pB.x, v1[2]);
                    v0[3] = f2fma(wqA, pB.y, v0[3]); v1[3] = f2fma(wqB, pB.y, v1[3]);
                }
                {
                    ull wqA = h2w(wA.z), wqB = h2w(wB.z);
                    ulonglong2 pA = pb2[4], pB = pb2[5];
                    v0[0] = f2fma(wqA, pA.x, v0[0]); v1[0] = f2fma(wqB, pA.x, v1[0]);
                    v0[1] = f2fma(wqA, pA.y, v0[1]); v1[1] = f2fma(wqB, pA.y, v1[1]);
                    v0[2] = f2fma(wqA, pB.x, v0[2]); v1[2] = f2fma(wqB, pB.x, v1[2]);
                    v0[3] = f2fma(wqA, pB.y, v0[3]); v1[3] = f2fma(wqB, pB.y, v1[3]);
                }
                {
                    ull wqA = h2w(wA.w), wqB = h2w(wB.w);
                    ulonglong2 pA = pb2[6], pB = pb2[7];
                    v0[0] = f2fma(wqA, pA.x, v0[0]); v1[0] = f2fma(wqB, pA.x, v1[0]);
                    v0[1] = f2fma(wqA, pA.y, v0[1]); v1[1] = f2fma(wqB, pA.y, v1[1]);
                    v0[2] = f2fma(wqA, pB.x, v0[2]); v1[2] = f2fma(wqB, pB.x, v1[2]);
                    v0[3] = f2fma(wqA, pB.y, v0[3]); v1[3] = f2fma(wqB, pB.y, v1[3]);
                }
                ull ssd2;
                {
                    ull dd = f2add(v0[0], nmu0[0]);
                    ssd2 = f2mul(dd, dd);
                }
                #pragma unroll
                for (int r = 1; r < 4; r++) {
                    ull dd = f2add(v0[r], nmu0[r]);
                    ssd2 = f2fma(dd, dd, ssd2);
                }
                #pragma unroll
                for (int r = 0; r < 4; r++) {
                    ull dd = f2add(v1[r], nmu1[r]);
                    ssd2 = f2fma(dd, dd, ssd2);
                }
                float slo, shi; f2unpack(slo, shi, ssd2);
                float ph = sf * __expf(-(slo + shi));
                // kperm=[0,2,1] self-inverse: file p_hat at permuted slot
                int o = oij / 9, ij = oij - o * 9;
                int i2 = ij / 3, j2 = ij - i2 * 3;
                ph_s[(o * 9 + ((3 - i2) % 3) * 3 + ((3 - j2) % 3)) * 33 + c] = ph;
                wA = wAn; wB = wBn;
            }
        }
        __syncthreads();

        // ---- D pass: row sums -> global atomics ----
        float* Dg = (it == 0) ? g_D0 : g_D1;
        for (int row = tid; row < 288; row += 256) {
            const float* pr = ph_s + row * 33;
            float s = 0.0f;
            #pragma unroll
            for (int k = 0; k < 32; k++) s += pr[k];
            int o = row / 9, ij = row - o * 9;
            atomicAdd(&Dg[(n * 32 + o) * 169 + (2 * X + ij / 3) * 13 + (2 * Y + ij % 3)], s);
        }

        // ---- grid barrier (288 blocks, 2/SM provably co-resident) ----
        __syncthreads();
        if (tid == 0) {
            __threadfence();
            atomicAdd(&g_bar[it], 1u);
            while (*((volatile unsigned*)&g_bar[it]) < 288u) { __nanosleep(32); }
        }
        __syncthreads();

        // ---- aD pass: a / D ----
        for (int e = tid; e < 288; e += 256) {
            int o = e / 9, ij = e - o * 9;
            float Dv = __ldcg(&Dg[(n * 32 + o) * 169 + (2 * X + ij / 3) * 13 + (2 * Y + ij % 3)]);
            aD_s[e] = __fdividef(a_s[e], Dv);
        }
        __syncthreads();
    }
}

extern "C" void kernel_launch(void* const* d_in, const int* in_sizes, int n_in,
                              void* d_out, int out_size) {
    const float* x   = (const float*)d_in[0];
    const float* W   = (const float*)d_in[1];
    const float* bv  = (const float*)d_in[2];
    const float* ba  = (const float*)d_in[3];
    const float* lam = (const float*)d_in[4];
    float* out = (float*)d_out;

    const int smem = SMEM_FLOATS * 4;   // 83712 B
    cudaFuncSetAttribute(fused_kernel, cudaFuncAttributeMaxDynamicSharedMemorySize, smem);

    prep_kernel<<<576, 256>>>(W);
    fused_kernel<<<dim3(36, 8), 256, smem>>>(x, bv, ba, lam, out);
}

// round 11
// speedup vs baseline: 1.1762x; 1.0382x over previous
#include <cuda_runtime.h>
#include <math.h>

// ConvCaps EM routing (b=8, B=C=32, K=3, s=2, Win=13, Wout=6, 3 EM iters).
// R11: R4 datapath (fp32 W, packed f32x2, zero conversion overhead) + the
// R10-validated software prefetch (issue% +6pp there), flat 36-position loop,
// dual ssd chains in E. 256 thr, 2 blocks/SM.
// p_hat block-local in smem; grid barrier only for the D normalizer.

#define RP0 (1.0f / 1152.0f)
#define LOG2PI 1.8378770664093453f
typedef unsigned long long ull;

__device__ float g_Wt[147456];   // [o][ij][q][c][p]  (ulonglong2 per (q,c))
__device__ float g_D0[43264];    // [n][o][13][13]
__device__ float g_D1[43264];
__device__ unsigned g_bar[2];

// -------- prep: W relayout, zero D + barrier counters --------
__global__ void prep_kernel(const float* __restrict__ W) {
    int idx = blockIdx.x * 256 + threadIdx.x;
    if (idx < 147456) {
        int p = idx & 3, c = (idx >> 2) & 31, q = (idx >> 7) & 3;
        int oij = idx >> 9;
        int o = oij / 9, ij = oij - o * 9;
        // src: W[i,j,o,c,p,q]
        g_Wt[idx] = W[(((ij * 32 + o) * 32 + c) * 4 + p) * 4 + q];
    }
    if (idx < 43264) { g_D0[idx] = 0.0f; g_D1[idx] = 0.0f; }
    if (idx < 2) g_bar[idx] = 0u;
}

// -------- packed f32x2 helpers --------
__device__ __forceinline__ ull f2fma(ull a, ull b, ull c) {
    ull d; asm("fma.rn.f32x2 %0, %1, %2, %3;" : "=l"(d) : "l"(a), "l"(b), "l"(c)); return d;
}
__device__ __forceinline__ ull f2mul(ull a, ull b) {
    ull d; asm("mul.rn.f32x2 %0, %1, %2;" : "=l"(d) : "l"(a), "l"(b)); return d;
}
__device__ __forceinline__ ull f2add(ull a, ull b) {
    ull d; asm("add.rn.f32x2 %0, %1, %2;" : "=l"(d) : "l"(a), "l"(b)); return d;
}
__device__ __forceinline__ ull f2pack(float lo, float hi) {
    ull d; asm("mov.b64 %0, {%1, %2};" : "=l"(d) : "f"(lo), "f"(hi)); return d;
}
__device__ __forceinline__ void f2unpack(float& lo, float& hi, ull v) {
    asm("mov.b64 {%0, %1}, %2;" : "=f"(lo), "=f"(hi) : "l"(v));
}

// smem float offsets
#define SM_POSE2 0        // [oij][qr][2] duplicated pose: 9216
#define SM_A     9216     // 288
#define SM_AD    9504     // 288
#define SM_PH    9792     // [oij][33] p_hat (red 8*1056=8448 aliased): 9504
#define SM_MOM   19296    // [c][33]: 1056
#define SM_MU    20352    // [c][17]: 544
#define SM_SFAC  20896    // 32
#define SMEM_FLOATS 20928

__global__ void __launch_bounds__(256, 2) fused_kernel(
    const float* __restrict__ x,
    const float* __restrict__ bv_p,
    const float* __restrict__ ba_p,
    const float* __restrict__ lam_p,
    float* __restrict__ out)
{
    extern __shared__ float sm[];
    float* pose2  = sm + SM_POSE2;
    float* a_s    = sm + SM_A;
    float* aD_s   = sm + SM_AD;
    float* ph_s   = sm + SM_PH;
    float* red    = ph_s;          // aliased: red live only between M and stats
    float* mom    = sm + SM_MOM;
    float* mu_s   = sm + SM_MU;
    float* sfac_s = sm + SM_SFAC;

    const int xy = blockIdx.x;     // 0..35
    const int n  = blockIdx.y;     // 0..7
    const int X = xy / 6, Y = xy % 6;
    const int tid = threadIdx.x;
    const int w = tid >> 5;        // warp 0..7 -> positions w*36 .. w*36+35
    const int c = tid & 31;        // lane = output capsule

    const float* xn = x + n * (544 * 169);
    const int base = (2 * X) * 13 + 2 * Y;

    // ---- load patch: duplicated pose (qr-inner), act ----
    for (int e = tid; e < 512; e += 256) {
        int qr = e & 15, o = e >> 4;
        const float* src = xn + (qr * 32 + o) * 169 + base;
        #pragma unroll
        for (int i = 0; i < 3; i++)
            #pragma unroll
            for (int j = 0; j < 3; j++) {
                float v = src[i * 13 + j];
                int off = (o * 9 + i * 3 + j) * 32 + qr * 2;
                pose2[off] = v; pose2[off + 1] = v;
            }
    }
    for (int e = tid; e < 288; e += 256) {
        int o = e / 9, ij = e - o * 9;
        float av = xn[(512 + o) * 169 + base + (ij / 3) * 13 + (ij % 3)];
        a_s[e] = av;
        aD_s[e] = av * RP0;        // iter0: rh = ph(=1) * aD
    }
    for (int e = tid; e < 9504; e += 256) ph_s[e] = 1.0f;
    __syncthreads();

    const float bv = bv_p[0], ba = ba_p[0], lam = lam_p[0];
    // W base for this warp's 36 positions: ulonglong2 index (oij*4+q)*32 + c
    const ulonglong2* wbase = (const ulonglong2*)g_Wt + (w * 36 * 4) * 32 + c;

    for (int it = 0; it < 3; it++) {
        // ================= M phase (pipelined W prefetch) =================
        ull m1a[4], m1b[4], m2a[4], m2b[4];
        #pragma unroll
        for (int r = 0; r < 4; r++) { m1a[r]=0ull; m1b[r]=0ull; m2a[r]=0ull; m2b[r]=0ull; }
        float sumr = 0.0f;

        ulonglong2 wv0 = wbase[0], wv1 = wbase[32], wv2 = wbase[64], wv3 = wbase[96];
        #pragma unroll 4
        for (int k = 0; k < 36; k++) {
            ulonglong2 n0 = wv0, n1 = wv1, n2 = wv2, n3 = wv3;
            if (k < 35) {
                const ulonglong2* nw = wbase + (k + 1) * 128;
                n0 = nw[0]; n1 = nw[32]; n2 = nw[64]; n3 = nw[96];
            }
            int oij = w * 36 + k;
            float rh = ph_s[oij * 33 + c] * aD_s[oij];
            sumr += rh;
            ull rh2 = f2pack(rh, rh);
            const ulonglong2* pb2 = (const ulonglong2*)(pose2 + oij * 32);
            ull v0[4], v1[4];
            {
                ulonglong2 pA = pb2[0], pB = pb2[1];     // q=0: dup P r0..r3
                v0[0] = f2mul(wv0.x, pA.x); v1[0] = f2mul(wv0.y, pA.x);
                v0[1] = f2mul(wv0.x, pA.y); v1[1] = f2mul(wv0.y, pA.y);
                v0[2] = f2mul(wv0.x, pB.x); v1[2] = f2mul(wv0.y, pB.x);
                v0[3] = f2mul(wv0.x, pB.y); v1[3] = f2mul(wv0.y, pB.y);
            }
            {
                ulonglong2 pA = pb2[2], pB = pb2[3];
                v0[0] = f2fma(wv1.x, pA.x, v0[0]); v1[0] = f2fma(wv1.y, pA.x, v1[0]);
                v0[1] = f2fma(wv1.x, pA.y, v0[1]); v1[1] = f2fma(wv1.y, pA.y, v1[1]);
                v0[2] = f2fma(wv1.x, pB.x, v0[2]); v1[2] = f2fma(wv1.y, pB.x, v1[2]);
                v0[3] = f2fma(wv1.x, pB.y, v0[3]); v1[3] = f2fma(wv1.y, pB.y, v1[3]);
            }
            {
                ulonglong2 pA = pb2[4], pB = pb2[5];
                v0[0] = f2fma(wv2.x, pA.x, v0[0]); v1[0] = f2fma(wv2.y, pA.x, v1[0]);
                v0[1] = f2fma(wv2.x, pA.y, v0[1]); v1[1] = f2fma(wv2.y, pA.y, v1[1]);
                v0[2] = f2fma(wv2.x, pB.x, v0[2]); v1[2] = f2fma(wv2.y, pB.x, v1[2]);
                v0[3] = f2fma(wv2.x, pB.y, v0[3]); v1[3] = f2fma(wv2.y, pB.y, v1[3]);
            }
            {
                ulonglong2 pA = pb2[6], pB = pb2[7];
                v0[0] = f2fma(wv3.x, pA.x, v0[0]); v1[0] = f2fma(wv3.y, pA.x, v1[0]);
                v0[1] = f2fma(wv3.x, pA.y, v0[1]); v1[1] = f2fma(wv3.y, pA.y, v1[1]);
                v0[2] = f2fma(wv3.x, pB.x, v0[2]); v1[2] = f2fma(wv3.y, pB.x, v1[2]);
                v0[3] = f2fma(wv3.x, pB.y, v0[3]); v1[3] = f2fma(wv3.y, pB.y, v1[3]);
            }
            #pragma unroll
            for (int r = 0; r < 4; r++) {
                ull t0 = f2mul(rh2, v0[r]);
                m1a[r] = f2add(m1a[r], t0);
                m2a[r] = f2fma(t0, v0[r], m2a[r]);
                ull t1 = f2mul(rh2, v1[r]);
                m1b[r] = f2add(m1b[r], t1);
                m2b[r] = f2fma(t1, v1[r], m2b[r]);
            }
            wv0 = n0; wv1 = n1; wv2 = n2; wv3 = n3;
        }
        __syncthreads();   // all ph reads done before red overwrites it

        // pair layout: v0[r] = (d=r, d=4+r), v1[r] = (d=8+r, d=12+r)
        {
            float* myred = red + (w * 32 + c) * 33;
            #pragma unroll
            for (int r = 0; r < 4; r++) {
                float lo, hi;
                f2unpack(lo, hi, m1a[r]); myred[r]      = lo; myred[4 + r]  = hi;
                f2unpack(lo, hi, m1b[r]); myred[8 + r]  = lo; myred[12 + r] = hi;
                f2unpack(lo, hi, m2a[r]); myred[16 + r] = lo; myred[20 + r] = hi;
                f2unpack(lo, hi, m2b[r]); myred[24 + r] = lo; myred[28 + r] = hi;
            }
            myred[32] = sumr;
        }
        __syncthreads();
        for (int s = tid; s < 1056; s += 256) {
            float acc = 0.0f;
            #pragma unroll
            for (int ww = 0; ww < 8; ww++) acc += red[ww * 1056 + s];
            mom[s] = acc;
        }
        __syncthreads();

        // ================= stats =================
        if (tid < 32) {
            const float* mm = mom + tid * 33;
            float R = mm[32];
            float invR = 1.0f / R;
            float cs = 0.0f;
            #pragma unroll
            for (int d = 0; d < 16; d++) {
                float m  = mm[d] * invR;
                float sg = fmaf(-m, m, mm[16 + d] * invR);
                mu_s[tid * 17 + d] = m;
                cs += __logf(sg);
            }
            float cost = R * fmaf(16.0f, bv, cs);
            float act  = 1.0f / (1.0f + __expf(lam * (cost - ba)));
            if (it == 2) {
                float* on = out + (long)n * 19584 + xy;
                #pragma unroll
                for (int d = 0; d < 16; d++)
                    on[(tid * 16 + d) * 36] = mu_s[tid * 17 + d];
                on[(512 + tid) * 36] = act;
            } else {
                sfac_s[tid] = act * __expf(-0.5f * fmaf(16.0f, LOG2PI, cs));
            }
        }
        __syncthreads();
        if (it == 2) return;

        // ================= E phase (pipelined W prefetch) =================
        {
            float sf = sfac_s[c];
            ull nmu0[4], nmu1[4];
            #pragma unroll
            for (int r = 0; r < 4; r++) {
                nmu0[r] = f2pack(-mu_s[c * 17 + r],     -mu_s[c * 17 + 4 + r]);
                nmu1[r] = f2pack(-mu_s[c * 17 + 8 + r], -mu_s[c * 17 + 12 + r]);
            }
            ulonglong2 wv0 = wbase[0], wv1 = wbase[32], wv2 = wbase[64], wv3 = wbase[96];
            #pragma unroll 4
            for (int k = 0; k < 36; k++) {
                ulonglong2 n0 = wv0, n1 = wv1, n2 = wv2, n3 = wv3;
                if (k < 35) {
                    const ulonglong2* nw = wbase + (k + 1) * 128;
                    n0 = nw[0]; n1 = nw[32]; n2 = nw[64]; n3 = nw[96];
                }
                int oij = w * 36 + k;
                const ulonglong2* pb2 = (const ulonglong2*)(pose2 + oij * 32);
                ull v0[4], v1[4];
                {
                    ulonglong2 pA = pb2[0], pB = pb2[1];
                    v0[0] = f2mul(wv0.x, pA.x); v1[0] = f2mul(wv0.y, pA.x);
                    v0[1] = f2mul(wv0.x, pA.y); v1[1] = f2mul(wv0.y, pA.y);
                    v0[2] = f2mul(wv0.x, pB.x); v1[2] = f2mul(wv0.y, pB.x);
                    v0[3] = f2mul(wv0.x, pB.y); v1[3] = f2mul(wv0.y, pB.y);
                }
                {
                    ulonglong2 pA = pb2[2], pB = pb2[3];
                    v0[0] = f2fma(wv1.x, pA.x, v0[0]); v1[0] = f2fma(wv1.y, pA.x, v1[0]);
                    v0[1] = f2fma(wv1.x, pA.y, v0[1]); v1[1] = f2fma(wv1.y, pA.y, v1[1]);
                    v0[2] = f2fma(wv1.x, pB.x, v0[2]); v1[2] = f2fma(wv1.y, pB.x, v1[2]);
                    v0[3] = f2fma(wv1.x, pB.y, v0[3]); v1[3] = f2fma(wv1.y, pB.y, v1[3]);
                }
                {
                    ulonglong2 pA = pb2[4], pB = pb2[5];
                    v0[0] = f2fma(wv2.x, pA.x, v0[0]); v1[0] = f2fma(wv2.y, pA.x, v1[0]);
                    v0[1] = f2fma(wv2.x, pA.y, v0[1]); v1[1] = f2fma(wv2.y, pA.y, v1[1]);
                    v0[2] = f2fma(wv2.x, pB.x, v0[2]); v1[2] = f2fma(wv2.y, pB.x, v1[2]);
                    v0[3] = f2fma(wv2.x, pB.y, v0[3]); v1[3] = f2fma(wv2.y, pB.y, v1[3]);
                }
                {
                    ulonglong2 pA = pb2[6], pB = pb2[7];
                    v0[0] = f2fma(wv3.x, pA.x, v0[0]); v1[0] = f2fma(wv3.y, pA.x, v1[0]);
                    v0[1] = f2fma(wv3.x, pA.y, v0[1]); v1[1] = f2fma(wv3.y, pA.y, v1[1]);
                    v0[2] = f2fma(wv3.x, pB.x, v0[2]); v1[2] = f2fma(wv3.y, pB.x, v1[2]);
                    v0[3] = f2fma(wv3.x, pB.y, v0[3]); v1[3] = f2fma(wv3.y, pB.y, v1[3]);
                }
                // dual ssd chains (halve the dependency chain)
                ull sa, sb;
                {
                    ull d0 = f2add(v0[0], nmu0[0]); sa = f2mul(d0, d0);
                    ull d1 = f2add(v0[1], nmu0[1]); sb = f2mul(d1, d1);
                }
                {
                    ull d0 = f2add(v0[2], nmu0[2]); sa = f2fma(d0, d0, sa);
                    ull d1 = f2add(v0[3], nmu0[3]); sb = f2fma(d1, d1, sb);
                }
                {
                    ull d0 = f2add(v1[0], nmu1[0]); sa = f2fma(d0, d0, sa);
                    ull d1 = f2add(v1[1], nmu1[1]); sb = f2fma(d1, d1, sb);
                }
                {
                    ull d0 = f2add(v1[2], nmu1[2]); sa = f2fma(d0, d0, sa);
                    ull d1 = f2add(v1[3], nmu1[3]); sb = f2fma(d1, d1, sb);
                }
                ull ssd2 = f2add(sa, sb);
                float slo, shi; f2unpack(slo, shi, ssd2);
                float ph = sf * __expf(-(slo + shi));
                // kperm=[0,2,1] self-inverse: file p_hat at permuted slot
                int o = oij / 9, ij = oij - o * 9;
                int i2 = ij / 3, j2 = ij - i2 * 3;
                ph_s[(o * 9 + ((3 - i2) % 3) * 3 + ((3 - j2) % 3)) * 33 + c] = ph;
                wv0 = n0; wv1 = n1; wv2 = n2; wv3 = n3;
            }
        }
        __syncthreads();

        // ---- D pass: row sums -> global atomics ----
        float* Dg = (it == 0) ? g_D0 : g_D1;
        for (int row = tid; row < 288; row += 256) {
            const float* pr = ph_s + row * 33;
            float s = 0.0f;
            #pragma unroll
            for (int k = 0; k < 32; k++) s += pr[k];
            int o = row / 9, ij = row - o * 9;
            atomicAdd(&Dg[(n * 32 + o) * 169 + (2 * X + ij / 3) * 13 + (2 * Y + ij % 3)], s);
        }

        // ---- grid barrier (288 blocks, 2/SM provably co-resident) ----
        __syncthreads();
        if (tid == 0) {
            __threadfence();
            atomicAdd(&g_bar[it], 1u);
            while (*((volatile unsigned*)&g_bar[it]) < 288u) { __nanosleep(32); }
        }
        __syncthreads();

        // ---- aD pass: a / D ----
        for (int e = tid; e < 288; e += 256) {
            int o = e / 9, ij = e - o * 9;
            float Dv = __ldcg(&Dg[(n * 32 + o) * 169 + (2 * X + ij / 3) * 13 + (2 * Y + ij % 3)]);
            aD_s[e] = __fdividef(a_s[e], Dv);
        }
        __syncthreads();
    }
}

extern "C" void kernel_launch(void* const* d_in, const int* in_sizes, int n_in,
                              void* d_out, int out_size) {
    const float* x   = (const float*)d_in[0];
    const float* W   = (const float*)d_in[1];
    const float* bv  = (const float*)d_in[2];
    const float* ba  = (const float*)d_in[3];
    const float* lam = (const float*)d_in[4];
    float* out = (float*)d_out;

    const int smem = SMEM_FLOATS * 4;   // 83712 B
    cudaFuncSetAttribute(fused_kernel, cudaFuncAttributeMaxDynamicSharedMemorySize, smem);

    prep_kernel<<<576, 256>>>(W);
    fused_kernel<<<dim3(36, 8), 256, smem>>>(x, bv, ba, lam, out);
}

// round 12
// speedup vs baseline: 1.4073x; 1.1966x over previous
#include <cuda_runtime.h>
#include <cuda_fp16.h>
#include <math.h>

// ConvCaps EM routing (b=8, B=C=32, K=3, s=2, Win=13, Wout=6, 3 EM iters).
// R12: votes are iteration-invariant -> compute ONCE (M0, fp32 pose x W),
// cache fp16 in an 85 MB global buffer (L2-resident), and the remaining 4
// sweeps (E0, M1, E1, M2) stream them back with 2 prefetched LDG.128/position.
// ~29% fewer issue slots than R11. 256 thr, 2 blocks/SM, packed f32x2 math.
// p_hat block-local in smem; grid barrier only for the D normalizer.

#define RP0 (1.0f / 1152.0f)
#define LOG2PI 1.8378770664093453f
typedef unsigned long long ull;

__device__ float g_Wt[147456];        // [o][ij][q][c][p]  (ulonglong2 per (q,c))
__device__ __half g_votes[42467328];  // [n][xy][oij][g][c][8]  85 MB, L2-resident
__device__ float g_D0[43264];         // [n][o][13][13]
__device__ float g_D1[43264];
__device__ unsigned g_bar[2];

// -------- prep: W relayout, zero D + barrier counters --------
__global__ void prep_kernel(const float* __restrict__ W) {
    int idx = blockIdx.x * 256 + threadIdx.x;
    if (idx < 147456) {
        int p = idx & 3, c = (idx >> 2) & 31, q = (idx >> 7) & 3;
        int oij = idx >> 9;
        int o = oij / 9, ij = oij - o * 9;
        // src: W[i,j,o,c,p,q]
        g_Wt[idx] = W[(((ij * 32 + o) * 32 + c) * 4 + p) * 4 + q];
    }
    if (idx < 43264) { g_D0[idx] = 0.0f; g_D1[idx] = 0.0f; }
    if (idx < 2) g_bar[idx] = 0u;
}

// -------- packed f32x2 helpers --------
__device__ __forceinline__ ull f2fma(ull a, ull b, ull c) {
    ull d; asm("fma.rn.f32x2 %0, %1, %2, %3;" : "=l"(d) : "l"(a), "l"(b), "l"(c)); return d;
}
__device__ __forceinline__ ull f2mul(ull a, ull b) {
    ull d; asm("mul.rn.f32x2 %0, %1, %2;" : "=l"(d) : "l"(a), "l"(b)); return d;
}
__device__ __forceinline__ ull f2add(ull a, ull b) {
    ull d; asm("add.rn.f32x2 %0, %1, %2;" : "=l"(d) : "l"(a), "l"(b)); return d;
}
__device__ __forceinline__ ull f2pack(float lo, float hi) {
    ull d; asm("mov.b64 %0, {%1, %2};" : "=l"(d) : "f"(lo), "f"(hi)); return d;
}
__device__ __forceinline__ void f2unpack(float& lo, float& hi, ull v) {
    asm("mov.b64 {%0, %1}, %2;" : "=f"(lo), "=f"(hi) : "l"(v));
}
__device__ __forceinline__ unsigned f2h2(ull v) {    // packed f32x2 -> half2
    float lo, hi; f2unpack(lo, hi, v);
    unsigned r; asm("cvt.rn.f16x2.f32 %0, %1, %2;" : "=r"(r) : "f"(hi), "f"(lo));
    return r;
}
__device__ __forceinline__ ull h2w(unsigned u) {     // half2 -> packed f32x2
    __half2 h = *reinterpret_cast<__half2*>(&u);
    float2 f = __half22float2(h);
    return f2pack(f.x, f.y);
}

// smem float offsets
#define SM_POSE2 0        // [oij][qr][2] duplicated pose: 9216
#define SM_A     9216     // 288
#define SM_AD    9504     // 288
#define SM_PH    9792     // [oij][33] p_hat (red 8*1056=8448 aliased): 9504
#define SM_MOM   19296    // [c][33]: 1056
#define SM_MU    20352    // [c][17]: 544
#define SM_SFAC  20896    // 32
#define SMEM_FLOATS 20928

__global__ void __launch_bounds__(256, 2) fused_kernel(
    const float* __restrict__ x,
    const float* __restrict__ bv_p,
    const float* __restrict__ ba_p,
    const float* __restrict__ lam_p,
    float* __restrict__ out)
{
    extern __shared__ float sm[];
    float* pose2  = sm + SM_POSE2;
    float* a_s    = sm + SM_A;
    float* aD_s   = sm + SM_AD;
    float* ph_s   = sm + SM_PH;
    float* red    = ph_s;          // aliased: red live only between M and stats
    float* mom    = sm + SM_MOM;
    float* mu_s   = sm + SM_MU;
    float* sfac_s = sm + SM_SFAC;

    const int xy = blockIdx.x;     // 0..35
    const int n  = blockIdx.y;     // 0..7
    const int X = xy / 6, Y = xy % 6;
    const int tid = threadIdx.x;
    const int w = tid >> 5;        // warp 0..7 -> positions w*36 .. w*36+35
    const int c = tid & 31;        // lane = output capsule

    const float* xn = x + n * (544 * 169);
    const int base = (2 * X) * 13 + 2 * Y;

    // ---- load patch: duplicated pose (qr-inner), act ----
    for (int e = tid; e < 512; e += 256) {
        int qr = e & 15, o = e >> 4;
        const float* src = xn + (qr * 32 + o) * 169 + base;
        #pragma unroll
        for (int i = 0; i < 3; i++)
            #pragma unroll
            for (int j = 0; j < 3; j++) {
                float v = src[i * 13 + j];
                int off = (o * 9 + i * 3 + j) * 32 + qr * 2;
                pose2[off] = v; pose2[off + 1] = v;
            }
    }
    for (int e = tid; e < 288; e += 256) {
        int o = e / 9, ij = e - o * 9;
        float av = xn[(512 + o) * 169 + base + (ij / 3) * 13 + (ij % 3)];
        a_s[e] = av;
        aD_s[e] = av * RP0;        // iter0: rh = ph(=1) * aD
    }
    for (int e = tid; e < 9504; e += 256) ph_s[e] = 1.0f;
    __syncthreads();

    const float bv = bv_p[0], ba = ba_p[0], lam = lam_p[0];
    const ulonglong2* wbase = (const ulonglong2*)g_Wt + (w * 36 * 4) * 32 + c;
    // vote cache base for this warp: uint4 index (((n*36+xy)*288 + oij)*2 + g)*32 + c
    uint4* vb = (uint4*)g_votes + (((n * 36 + xy) * 288 + w * 36) * 2) * 32 + c;

    for (int it = 0; it < 3; it++) {
        // ================= M phase =================
        ull m1a[4], m1b[4], m2a[4], m2b[4];
        #pragma unroll
        for (int r = 0; r < 4; r++) { m1a[r]=0ull; m1b[r]=0ull; m2a[r]=0ull; m2b[r]=0ull; }
        float sumr = 0.0f;

        if (it == 0) {
            // ---- M0: compute votes from pose x W, store fp16, moments ----
            #pragma unroll 2
            for (int k = 0; k < 36; k++) {
                int oij = w * 36 + k;
                const ulonglong2* wp = wbase + k * 128;
                ulonglong2 wv0 = wp[0], wv1 = wp[32], wv2 = wp[64], wv3 = wp[96];
                float rh = ph_s[oij * 33 + c] * aD_s[oij];
                sumr += rh;
                ull rh2 = f2pack(rh, rh);
                const ulonglong2* pb2 = (const ulonglong2*)(pose2 + oij * 32);
                ull v0[4], v1[4];
                {
                    ulonglong2 pA = pb2[0], pB = pb2[1];   // q=0: dup P r0..r3
                    v0[0] = f2mul(wv0.x, pA.x); v1[0] = f2mul(wv0.y, pA.x);
                    v0[1] = f2mul(wv0.x, pA.y); v1[1] = f2mul(wv0.y, pA.y);
                    v0[2] = f2mul(wv0.x, pB.x); v1[2] = f2mul(wv0.y, pB.x);
                    v0[3] = f2mul(wv0.x, pB.y); v1[3] = f2mul(wv0.y, pB.y);
                }
                {
                    ulonglong2 pA = pb2[2], pB = pb2[3];
                    v0[0] = f2fma(wv1.x, pA.x, v0[0]); v1[0] = f2fma(wv1.y, pA.x, v1[0]);
                    v0[1] = f2fma(wv1.x, pA.y, v0[1]); v1[1] = f2fma(wv1.y, pA.y, v1[1]);
                    v0[2] = f2fma(wv1.x, pB.x, v0[2]); v1[2] = f2fma(wv1.y, pB.x, v1[2]);
                    v0[3] = f2fma(wv1.x, pB.y, v0[3]); v1[3] = f2fma(wv1.y, pB.y, v1[3]);
                }
                {
                    ulonglong2 pA = pb2[4], pB = pb2[5];
                    v0[0] = f2fma(wv2.x, pA.x, v0[0]); v1[0] = f2fma(wv2.y, pA.x, v1[0]);
                    v0[1] = f2fma(wv2.x, pA.y, v0[1]); v1[1] = f2fma(wv2.y, pA.y, v1[1]);
                    v0[2] = f2fma(wv2.x, pB.x, v0[2]); v1[2] = f2fma(wv2.y, pB.x, v1[2]);
                    v0[3] = f2fma(wv2.x, pB.y, v0[3]); v1[3] = f2fma(wv2.y, pB.y, v1[3]);
                }
                {
                    ulonglong2 pA = pb2[6], pB = pb2[7];
                    v0[0] = f2fma(wv3.x, pA.x, v0[0]); v1[0] = f2fma(wv3.y, pA.x, v1[0]);
                    v0[1] = f2fma(wv3.x, pA.y, v0[1]); v1[1] = f2fma(wv3.y, pA.y, v1[1]);
                    v0[2] = f2fma(wv3.x, pB.x, v0[2]); v1[2] = f2fma(wv3.y, pB.x, v1[2]);
                    v0[3] = f2fma(wv3.x, pB.y, v0[3]); v1[3] = f2fma(wv3.y, pB.y, v1[3]);
                }
                // store votes fp16 (layout preserves the (d=r, d=4+r) pairing)
                uint4 s0, s1;
                s0.x = f2h2(v0[0]); s0.y = f2h2(v0[1]); s0.z = f2h2(v0[2]); s0.w = f2h2(v0[3]);
                s1.x = f2h2(v1[0]); s1.y = f2h2(v1[1]); s1.z = f2h2(v1[2]); s1.w = f2h2(v1[3]);
                vb[k * 64] = s0; vb[k * 64 + 32] = s1;
                #pragma unroll
                for (int r = 0; r < 4; r++) {
                    ull t0 = f2mul(rh2, v0[r]);
                    m1a[r] = f2add(m1a[r], t0);
                    m2a[r] = f2fma(t0, v0[r], m2a[r]);
                    ull t1 = f2mul(rh2, v1[r]);
                    m1b[r] = f2add(m1b[r], t1);
                    m2b[r] = f2fma(t1, v1[r], m2b[r]);
                }
            }
        } else {
            // ---- M-read: stream cached votes (prefetched), moments ----
            uint4 a0 = vb[0], a1 = vb[32];
            #pragma unroll 4
            for (int k = 0; k < 36; k++) {
                uint4 b0 = a0, b1 = a1;
                if (k < 35) { b0 = vb[(k + 1) * 64]; b1 = vb[(k + 1) * 64 + 32]; }
                int oij = w * 36 + k;
                float rh = ph_s[oij * 33 + c] * aD_s[oij];
                sumr += rh;
                ull rh2 = f2pack(rh, rh);
                ull sv0[4], sv1[4];
                sv0[0] = h2w(a0.x); sv0[1] = h2w(a0.y); sv0[2] = h2w(a0.z); sv0[3] = h2w(a0.w);
                sv1[0] = h2w(a1.x); sv1[1] = h2w(a1.y); sv1[2] = h2w(a1.z); sv1[3] = h2w(a1.w);
                #pragma unroll
                for (int r = 0; r < 4; r++) {
                    ull t0 = f2mul(rh2, sv0[r]);
                    m1a[r] = f2add(m1a[r], t0);
                    m2a[r] = f2fma(t0, sv0[r], m2a[r]);
                    ull t1 = f2mul(rh2, sv1[r]);
                    m1b[r] = f2add(m1b[r], t1);
                    m2b[r] = f2fma(t1, sv1[r], m2b[r]);
                }
                a0 = b0; a1 = b1;
            }
        }
        __syncthreads();   // all ph reads done before red overwrites it

        // pair layout: v0[r] = (d=r, d=4+r), v1[r] = (d=8+r, d=12+r)
        {
            float* myred = red + (w * 32 + c) * 33;
            #pragma unroll
            for (int r = 0; r < 4; r++) {
                float lo, hi;
                f2unpack(lo, hi, m1a[r]); myred[r]      = lo; myred[4 + r]  = hi;
                f2unpack(lo, hi, m1b[r]); myred[8 + r]  = lo; myred[12 + r] = hi;
                f2unpack(lo, hi, m2a[r]); myred[16 + r] = lo; myred[20 + r] = hi;
                f2unpack(lo, hi, m2b[r]); myred[24 + r] = lo; myred[28 + r] = hi;
            }
            myred[32] = sumr;
        }
        __syncthreads();
        for (int s = tid; s < 1056; s += 256) {
            float acc = 0.0f;
            #pragma unroll
            for (int ww = 0; ww < 8; ww++) acc += red[ww * 1056 + s];
            mom[s] = acc;
        }
        __syncthreads();

        // ================= stats =================
        if (tid < 32) {
            const float* mm = mom + tid * 33;
            float R = mm[32];
            float invR = 1.0f / R;
            float cs = 0.0f;
            #pragma unroll
            for (int d = 0; d < 16; d++) {
                float m  = mm[d] * invR;
                float sg = fmaf(-m, m, mm[16 + d] * invR);
                mu_s[tid * 17 + d] = m;
                cs += __logf(sg);
            }
            float cost = R * fmaf(16.0f, bv, cs);
            float act  = 1.0f / (1.0f + __expf(lam * (cost - ba)));
            if (it == 2) {
                float* on = out + (long)n * 19584 + xy;
                #pragma unroll
                for (int d = 0; d < 16; d++)
                    on[(tid * 16 + d) * 36] = mu_s[tid * 17 + d];
                on[(512 + tid) * 36] = act;
            } else {
                sfac_s[tid] = act * __expf(-0.5f * fmaf(16.0f, LOG2PI, cs));
            }
        }
        __syncthreads();
        if (it == 2) return;

        // ================= E phase: stream cached votes =================
        {
            float sf = sfac_s[c];
            ull nmu0[4], nmu1[4];
            #pragma unroll
            for (int r = 0; r < 4; r++) {
                nmu0[r] = f2pack(-mu_s[c * 17 + r],     -mu_s[c * 17 + 4 + r]);
                nmu1[r] = f2pack(-mu_s[c * 17 + 8 + r], -mu_s[c * 17 + 12 + r]);
            }
            uint4 a0 = vb[0], a1 = vb[32];
            #pragma unroll 4
            for (int k = 0; k < 36; k++) {
                uint4 b0 = a0, b1 = a1;
                if (k < 35) { b0 = vb[(k + 1) * 64]; b1 = vb[(k + 1) * 64 + 32]; }
                int oij = w * 36 + k;
                // dual ssd chains
                ull sa, sb;
                {
                    ull d0 = f2add(h2w(a0.x), nmu0[0]); sa = f2mul(d0, d0);
                    ull d1 = f2add(h2w(a0.y), nmu0[1]); sb = f2mul(d1, d1);
                }
                {
                    ull d0 = f2add(h2w(a0.z), nmu0[2]); sa = f2fma(d0, d0, sa);
                    ull d1 = f2add(h2w(a0.w), nmu0[3]); sb = f2fma(d1, d1, sb);
                }
                {
                    ull d0 = f2add(h2w(a1.x), nmu1[0]); sa = f2fma(d0, d0, sa);
                    ull d1 = f2add(h2w(a1.y), nmu1[1]); sb = f2fma(d1, d1, sb);
                }
                {
                    ull d0 = f2add(h2w(a1.z), nmu1[2]); sa = f2fma(d0, d0, sa);
                    ull d1 = f2add(h2w(a1.w), nmu1[3]); sb = f2fma(d1, d1, sb);
                }
                ull ssd2 = f2add(sa, sb);
                float slo, shi; f2unpack(slo, shi, ssd2);
                float ph = sf * __expf(-(slo + shi));
                // kperm=[0,2,1] self-inverse: file p_hat at permuted slot
                int o = oij / 9, ij = oij - o * 9;
                int i2 = ij / 3, j2 = ij - i2 * 3;
                ph_s[(o * 9 + ((3 - i2) % 3) * 3 + ((3 - j2) % 3)) * 33 + c] = ph;
                a0 = b0; a1 = b1;
            }
        }
        __syncthreads();

        // ---- D pass: row sums -> global atomics ----
        float* Dg = (it == 0) ? g_D0 : g_D1;
        for (int row = tid; row < 288; row += 256) {
            const float* pr = ph_s + row * 33;
            float s = 0.0f;
            #pragma unroll
            for (int k = 0; k < 32; k++) s += pr[k];
            int o = row / 9, ij = row - o * 9;
            atomicAdd(&Dg[(n * 32 + o) * 169 + (2 * X + ij / 3) * 13 + (2 * Y + ij % 3)], s);
        }

        // ---- grid barrier (288 blocks, 2/SM provably co-resident) ----
        __syncthreads();
        if (tid == 0) {
            __threadfence();
            atomicAdd(&g_bar[it], 1u);
            while (*((volatile unsigned*)&g_bar[it]) < 288u) { __nanosleep(32); }
        }
        __syncthreads();

        // ---- aD pass: a / D ----
        for (int e = tid; e < 288; e += 256) {
            int o = e / 9, ij = e - o * 9;
            float Dv = __ldcg(&Dg[(n * 32 + o) * 169 + (2 * X + ij / 3) * 13 + (2 * Y + ij % 3)]);
            aD_s[e] = __fdividef(a_s[e], Dv);
        }
        __syncthreads();
    }
}

extern "C" void kernel_launch(void* const* d_in, const int* in_sizes, int n_in,
                              void* d_out, int out_size) {
    const float* x   = (const float*)d_in[0];
    const float* W   = (const float*)d_in[1];
    const float* bv  = (const float*)d_in[2];
    const float* ba  = (const float*)d_in[3];
    const float* lam = (const float*)d_in[4];
    float* out = (float*)d_out;

    const int smem = SMEM_FLOATS * 4;   // 83712 B
    cudaFuncSetAttribute(fused_kernel, cudaFuncAttributeMaxDynamicSharedMemorySize, smem);

    prep_kernel<<<576, 256>>>(W);
    fused_kernel<<<dim3(36, 8), 256, smem>>>(x, bv, ba, lam, out);
}

// round 13
// speedup vs baseline: 1.4079x; 1.0004x over previous
#include <cuda_runtime.h>
#include <cuda_fp16.h>
#include <math.h>

// ConvCaps EM routing (b=8, B=C=32, K=3, s=2, Win=13, Wout=6, 3 EM iters).
// R13 = R12 (votes computed once in M0, cached fp16 in 85 MB L2-resident
// buffer, 4 read sweeps) + latency fixes: depth-2 prefetch in read sweeps
// (covers the ~250-cyc L2 hit), W distance-1 prefetch in M0, __ldcg votes.
// 256 thr, 2 blocks/SM, packed f32x2 math.
// p_hat block-local in smem; grid barrier only for the D normalizer.

#define RP0 (1.0f / 1152.0f)
#define LOG2PI 1.8378770664093453f
typedef unsigned long long ull;

__device__ float g_Wt[147456];        // [o][ij][q][c][p]  (ulonglong2 per (q,c))
__device__ __half g_votes[42467328];  // [n][xy][oij][g][c][8]  85 MB, L2-resident
__device__ float g_D0[43264];         // [n][o][13][13]
__device__ float g_D1[43264];
__device__ unsigned g_bar[2];

// -------- prep: W relayout, zero D + barrier counters --------
__global__ void prep_kernel(const float* __restrict__ W) {
    int idx = blockIdx.x * 256 + threadIdx.x;
    if (idx < 147456) {
        int p = idx & 3, c = (idx >> 2) & 31, q = (idx >> 7) & 3;
        int oij = idx >> 9;
        int o = oij / 9, ij = oij - o * 9;
        // src: W[i,j,o,c,p,q]
        g_Wt[idx] = W[(((ij * 32 + o) * 32 + c) * 4 + p) * 4 + q];
    }
    if (idx < 43264) { g_D0[idx] = 0.0f; g_D1[idx] = 0.0f; }
    if (idx < 2) g_bar[idx] = 0u;
}

// -------- packed f32x2 helpers --------
__device__ __forceinline__ ull f2fma(ull a, ull b, ull c) {
    ull d; asm("fma.rn.f32x2 %0, %1, %2, %3;" : "=l"(d) : "l"(a), "l"(b), "l"(c)); return d;
}
__device__ __forceinline__ ull f2mul(ull a, ull b) {
    ull d; asm("mul.rn.f32x2 %0, %1, %2;" : "=l"(d) : "l"(a), "l"(b)); return d;
}
__device__ __forceinline__ ull f2add(ull a, ull b) {
    ull d; asm("add.rn.f32x2 %0, %1, %2;" : "=l"(d) : "l"(a), "l"(b)); return d;
}
__device__ __forceinline__ ull f2pack(float lo, float hi) {
    ull d; asm("mov.b64 %0, {%1, %2};" : "=l"(d) : "f"(lo), "f"(hi)); return d;
}
__device__ __forceinline__ void f2unpack(float& lo, float& hi, ull v) {
    asm("mov.b64 {%0, %1}, %2;" : "=f"(lo), "=f"(hi) : "l"(v));
}
__device__ __forceinline__ unsigned f2h2(ull v) {    // packed f32x2 -> half2
    float lo, hi; f2unpack(lo, hi, v);
    unsigned r; asm("cvt.rn.f16x2.f32 %0, %1, %2;" : "=r"(r) : "f"(hi), "f"(lo));
    return r;
}
__device__ __forceinline__ ull h2w(unsigned u) {     // half2 -> packed f32x2
    __half2 h = *reinterpret_cast<__half2*>(&u);
    float2 f = __half22float2(h);
    return f2pack(f.x, f.y);
}

// smem float offsets
#define SM_POSE2 0        // [oij][qr][2] duplicated pose: 9216
#define SM_A     9216     // 288
#define SM_AD    9504     // 288
#define SM_PH    9792     // [oij][33] p_hat (red 8*1056=8448 aliased): 9504
#define SM_MOM   19296    // [c][33]: 1056
#define SM_MU    20352    // [c][17]: 544
#define SM_SFAC  20896    // 32
#define SMEM_FLOATS 20928

__global__ void __launch_bounds__(256, 2) fused_kernel(
    const float* __restrict__ x,
    const float* __restrict__ bv_p,
    const float* __restrict__ ba_p,
    const float* __restrict__ lam_p,
    float* __restrict__ out)
{
    extern __shared__ float sm[];
    float* pose2  = sm + SM_POSE2;
    float* a_s    = sm + SM_A;
    float* aD_s   = sm + SM_AD;
    float* ph_s   = sm + SM_PH;
    float* red    = ph_s;          // aliased: red live only between M and stats
    float* mom    = sm + SM_MOM;
    float* mu_s   = sm + SM_MU;
    float* sfac_s = sm + SM_SFAC;

    const int xy = blockIdx.x;     // 0..35
    const int n  = blockIdx.y;     // 0..7
    const int X = xy / 6, Y = xy % 6;
    const int tid = threadIdx.x;
    const int w = tid >> 5;        // warp 0..7 -> positions w*36 .. w*36+35
    const int c = tid & 31;        // lane = output capsule

    const float* xn = x + n * (544 * 169);
    const int base = (2 * X) * 13 + 2 * Y;

    // ---- load patch: duplicated pose (qr-inner), act ----
    for (int e = tid; e < 512; e += 256) {
        int qr = e & 15, o = e >> 4;
        const float* src = xn + (qr * 32 + o) * 169 + base;
        #pragma unroll
        for (int i = 0; i < 3; i++)
            #pragma unroll
            for (int j = 0; j < 3; j++) {
                float v = src[i * 13 + j];
                int off = (o * 9 + i * 3 + j) * 32 + qr * 2;
                pose2[off] = v; pose2[off + 1] = v;
            }
    }
    for (int e = tid; e < 288; e += 256) {
        int o = e / 9, ij = e - o * 9;
        float av = xn[(512 + o) * 169 + base + (ij / 3) * 13 + (ij % 3)];
        a_s[e] = av;
        aD_s[e] = av * RP0;        // iter0: rh = ph(=1) * aD
    }
    for (int e = tid; e < 9504; e += 256) ph_s[e] = 1.0f;
    __syncthreads();

    const float bv = bv_p[0], ba = ba_p[0], lam = lam_p[0];
    const ulonglong2* wbase = (const ulonglong2*)g_Wt + (w * 36 * 4) * 32 + c;
    // vote cache base for this warp: uint4 index (((n*36+xy)*288 + oij)*2 + g)*32 + c
    uint4* vb = (uint4*)g_votes + (((n * 36 + xy) * 288 + w * 36) * 2) * 32 + c;

    for (int it = 0; it < 3; it++) {
        // ================= M phase =================
        ull m1a[4], m1b[4], m2a[4], m2b[4];
        #pragma unroll
        for (int r = 0; r < 4; r++) { m1a[r]=0ull; m1b[r]=0ull; m2a[r]=0ull; m2b[r]=0ull; }
        float sumr = 0.0f;

        if (it == 0) {
            // ---- M0: compute votes (W prefetch d=1), store fp16, moments ----
            ulonglong2 wv0 = wbase[0], wv1 = wbase[32], wv2 = wbase[64], wv3 = wbase[96];
            #pragma unroll 2
            for (int k = 0; k < 36; k++) {
                ulonglong2 n0 = wv0, n1 = wv1, n2 = wv2, n3 = wv3;
                if (k < 35) {
                    const ulonglong2* nw = wbase + (k + 1) * 128;
                    n0 = nw[0]; n1 = nw[32]; n2 = nw[64]; n3 = nw[96];
                }
                int oij = w * 36 + k;
                float rh = ph_s[oij * 33 + c] * aD_s[oij];
                sumr += rh;
                ull rh2 = f2pack(rh, rh);
                const ulonglong2* pb2 = (const ulonglong2*)(pose2 + oij * 32);
                ull v0[4], v1[4];
                {
                    ulonglong2 pA = pb2[0], pB = pb2[1];   // q=0: dup P r0..r3
                    v0[0] = f2mul(wv0.x, pA.x); v1[0] = f2mul(wv0.y, pA.x);
                    v0[1] = f2mul(wv0.x, pA.y); v1[1] = f2mul(wv0.y, pA.y);
                    v0[2] = f2mul(wv0.x, pB.x); v1[2] = f2mul(wv0.y, pB.x);
                    v0[3] = f2mul(wv0.x, pB.y); v1[3] = f2mul(wv0.y, pB.y);
                }
                {
                    ulonglong2 pA = pb2[2], pB = pb2[3];
                    v0[0] = f2fma(wv1.x, pA.x, v0[0]); v1[0] = f2fma(wv1.y, pA.x, v1[0]);
                    v0[1] = f2fma(wv1.x, pA.y, v0[1]); v1[1] = f2fma(wv1.y, pA.y, v1[1]);
                    v0[2] = f2fma(wv1.x, pB.x, v0[2]); v1[2] = f2fma(wv1.y, pB.x, v1[2]);
                    v0[3] = f2fma(wv1.x, pB.y, v0[3]); v1[3] = f2fma(wv1.y, pB.y, v1[3]);
                }
                {
                    ulonglong2 pA = pb2[4], pB = pb2[5];
                    v0[0] = f2fma(wv2.x, pA.x, v0[0]); v1[0] = f2fma(wv2.y, pA.x, v1[0]);
                    v0[1] = f2fma(wv2.x, pA.y, v0[1]); v1[1] = f2fma(wv2.y, pA.y, v1[1]);
                    v0[2] = f2fma(wv2.x, pB.x, v0[2]); v1[2] = f2fma(wv2.y, pB.x, v1[2]);
                    v0[3] = f2fma(wv2.x, pB.y, v0[3]); v1[3] = f2fma(wv2.y, pB.y, v1[3]);
                }
                {
                    ulonglong2 pA = pb2[6], pB = pb2[7];
                    v0[0] = f2fma(wv3.x, pA.x, v0[0]); v1[0] = f2fma(wv3.y, pA.x, v1[0]);
                    v0[1] = f2fma(wv3.x, pA.y, v0[1]); v1[1] = f2fma(wv3.y, pA.y, v1[1]);
                    v0[2] = f2fma(wv3.x, pB.x, v0[2]); v1[2] = f2fma(wv3.y, pB.x, v1[2]);
                    v0[3] = f2fma(wv3.x, pB.y, v0[3]); v1[3] = f2fma(wv3.y, pB.y, v1[3]);
                }
                // store votes fp16 (layout preserves the (d=r, d=4+r) pairing)
                uint4 s0, s1;
                s0.x = f2h2(v0[0]); s0.y = f2h2(v0[1]); s0.z = f2h2(v0[2]); s0.w = f2h2(v0[3]);
                s1.x = f2h2(v1[0]); s1.y = f2h2(v1[1]); s1.z = f2h2(v1[2]); s1.w = f2h2(v1[3]);
                vb[k * 64] = s0; vb[k * 64 + 32] = s1;
                #pragma unroll
                for (int r = 0; r < 4; r++) {
                    ull t0 = f2mul(rh2, v0[r]);
                    m1a[r] = f2add(m1a[r], t0);
                    m2a[r] = f2fma(t0, v0[r], m2a[r]);
                    ull t1 = f2mul(rh2, v1[r]);
                    m1b[r] = f2add(m1b[r], t1);
                    m2b[r] = f2fma(t1, v1[r], m2b[r]);
                }
                wv0 = n0; wv1 = n1; wv2 = n2; wv3 = n3;
            }
        } else {
            // ---- M-read: stream cached votes (depth-2 prefetch), moments ----
            uint4 a0 = __ldcg(vb), a1 = __ldcg(vb + 32);
            uint4 b0 = __ldcg(vb + 64), b1 = __ldcg(vb + 96);
            #pragma unroll 4
            for (int k = 0; k < 36; k++) {
                uint4 c0 = b0, c1 = b1;
                if (k < 34) { c0 = __ldcg(vb + (k + 2) * 64); c1 = __ldcg(vb + (k + 2) * 64 + 32); }
                int oij = w * 36 + k;
                float rh = ph_s[oij * 33 + c] * aD_s[oij];
                sumr += rh;
                ull rh2 = f2pack(rh, rh);
                ull sv0[4], sv1[4];
                sv0[0] = h2w(a0.x); sv0[1] = h2w(a0.y); sv0[2] = h2w(a0.z); sv0[3] = h2w(a0.w);
                sv1[0] = h2w(a1.x); sv1[1] = h2w(a1.y); sv1[2] = h2w(a1.z); sv1[3] = h2w(a1.w);
                #pragma unroll
                for (int r = 0; r < 4; r++) {
                    ull t0 = f2mul(rh2, sv0[r]);
                    m1a[r] = f2add(m1a[r], t0);
                    m2a[r] = f2fma(t0, sv0[r], m2a[r]);
                    ull t1 = f2mul(rh2, sv1[r]);
                    m1b[r] = f2add(m1b[r], t1);
                    m2b[r] = f2fma(t1, sv1[r], m2b[r]);
                }
                a0 = b0; a1 = b1; b0 = c0; b1 = c1;
            }
        }
        __syncthreads();   // all ph reads done before red overwrites it

        // pair layout: v0[r] = (d=r, d=4+r), v1[r] = (d=8+r, d=12+r)
        {
            float* myred = red + (w * 32 + c) * 33;
            #pragma unroll
            for (int r = 0; r < 4; r++) {
                float lo, hi;
                f2unpack(lo, hi, m1a[r]); myred[r]      = lo; myred[4 + r]  = hi;
                f2unpack(lo, hi, m1b[r]); myred[8 + r]  = lo; myred[12 + r] = hi;
                f2unpack(lo, hi, m2a[r]); myred[16 + r] = lo; myred[20 + r] = hi;
                f2unpack(lo, hi, m2b[r]); myred[24 + r] = lo; myred[28 + r] = hi;
            }
            myred[32] = sumr;
        }
        __syncthreads();
        for (int s = tid; s < 1056; s += 256) {
            float acc = 0.0f;
            #pragma unroll
            for (int ww = 0; ww < 8; ww++) acc += red[ww * 1056 + s];
            mom[s] = acc;
        }
        __syncthreads();

        // ================= stats =================
        if (tid < 32) {
            const float* mm = mom + tid * 33;
            float R = mm[32];
            float invR = 1.0f / R;
            float cs = 0.0f;
            #pragma unroll
            for (int d = 0; d < 16; d++) {
                float m  = mm[d] * invR;
                float sg = fmaf(-m, m, mm[16 + d] * invR);
                mu_s[tid * 17 + d] = m;
                cs += __logf(sg);
            }
            float cost = R * fmaf(16.0f, bv, cs);
            float act  = 1.0f / (1.0f + __expf(lam * (cost - ba)));
            if (it == 2) {
                float* on = out + (long)n * 19584 + xy;
                #pragma unroll
                for (int d = 0; d < 16; d++)
                    on[(tid * 16 + d) * 36] = mu_s[tid * 17 + d];
                on[(512 + tid) * 36] = act;
            } else {
                sfac_s[tid] = act * __expf(-0.5f * fmaf(16.0f, LOG2PI, cs));
            }
        }
        __syncthreads();
        if (it == 2) return;

        // ====== E phase: stream cached votes (depth-2 prefetch) ======
        {
            float sf = sfac_s[c];
            ull nmu0[4], nmu1[4];
            #pragma unroll
            for (int r = 0; r < 4; r++) {
                nmu0[r] = f2pack(-mu_s[c * 17 + r],     -mu_s[c * 17 + 4 + r]);
                nmu1[r] = f2pack(-mu_s[c * 17 + 8 + r], -mu_s[c * 17 + 12 + r]);
            }
            uint4 a0 = __ldcg(vb), a1 = __ldcg(vb + 32);
            uint4 b0 = __ldcg(vb + 64), b1 = __ldcg(vb + 96);
            #pragma unroll 4
            for (int k = 0; k < 36; k++) {
                uint4 c0 = b0, c1 = b1;
                if (k < 34) { c0 = __ldcg(vb + (k + 2) * 64); c1 = __ldcg(vb + (k + 2) * 64 + 32); }
                int oij = w * 36 + k;
                // dual ssd chains
                ull sa, sb;
                {
                    ull d0 = f2add(h2w(a0.x), nmu0[0]); sa = f2mul(d0, d0);
                    ull d1 = f2add(h2w(a0.y), nmu0[1]); sb = f2mul(d1, d1);
                }
                {
                    ull d0 = f2add(h2w(a0.z), nmu0[2]); sa = f2fma(d0, d0, sa);
                    ull d1 = f2add(h2w(a0.w), nmu0[3]); sb = f2fma(d1, d1, sb);
                }
                {
                    ull d0 = f2add(h2w(a1.x), nmu1[0]); sa = f2fma(d0, d0, sa);
                    ull d1 = f2add(h2w(a1.y), nmu1[1]); sb = f2fma(d1, d1, sb);
                }
                {
                    ull d0 = f2add(h2w(a1.z), nmu1[2]); sa = f2fma(d0, d0, sa);
                    ull d1 = f2add(h2w(a1.w), nmu1[3]); sb = f2fma(d1, d1, sb);
                }
                ull ssd2 = f2add(sa, sb);
                float slo, shi; f2unpack(slo, shi, ssd2);
                float ph = sf * __expf(-(slo + shi));
                // kperm=[0,2,1] self-inverse: file p_hat at permuted slot
                int o = oij / 9, ij = oij - o * 9;
                int i2 = ij / 3, j2 = ij - i2 * 3;
                ph_s[(o * 9 + ((3 - i2) % 3) * 3 + ((3 - j2) % 3)) * 33 + c] = ph;
                a0 = b0; a1 = b1; b0 = c0; b1 = c1;
            }
        }
        __syncthreads();

        // ---- D pass: row sums -> global atomics ----
        float* Dg = (it == 0) ? g_D0 : g_D1;
        for (int row = tid; row < 288; row += 256) {
            const float* pr = ph_s + row * 33;
            float s = 0.0f;
            #pragma unroll
            for (int k = 0; k < 32; k++) s += pr[k];
            int o = row / 9, ij = row - o * 9;
            atomicAdd(&Dg[(n * 32 + o) * 169 + (2 * X + ij / 3) * 13 + (2 * Y + ij % 3)], s);
        }

        // ---- grid barrier (288 blocks, 2/SM provably co-resident) ----
        __syncthreads();
        if (tid == 0) {
            __threadfence();
            atomicAdd(&g_bar[it], 1u);
            while (*((volatile unsigned*)&g_bar[it]) < 288u) { __nanosleep(32); }
        }
        __syncthreads();

        // ---- aD pass: a / D ----
        for (int e = tid; e < 288; e += 256) {
            int o = e / 9, ij = e - o * 9;
            float Dv = __ldcg(&Dg[(n * 32 + o) * 169 + (2 * X + ij / 3) * 13 + (2 * Y + ij % 3)]);
            aD_s[e] = __fdividef(a_s[e], Dv);
        }
        __syncthreads();
    }
}

extern "C" void kernel_launch(void* const* d_in, const int* in_sizes, int n_in,
                              void* d_out, int out_size) {
    const float* x   = (const float*)d_in[0];
    const float* W   = (const float*)d_in[1];
    const float* bv  = (const float*)d_in[2];
    const float* ba  = (const float*)d_in[3];
    const float* lam = (const float*)d_in[4];
    float* out = (float*)d_out;

    const int smem = SMEM_FLOATS * 4;   // 83712 B
    cudaFuncSetAttribute(fused_kernel, cudaFuncAttributeMaxDynamicSharedMemorySize, smem);

    prep_kernel<<<576, 256>>>(W);
    fused_kernel<<<dim3(36, 8), 256, smem>>>(x, bv, ba, lam, out);
}